// round 6
// baseline (speedup 1.0000x reference)
#include <cuda_runtime.h>

#define N_NODES 100000
#define N_EDGES 400000
#define BATCH   2048
#define HD      128
#define NREL    100

// ---------------- scratch ----------------
__device__ __align__(16) float g_h[(size_t)N_NODES * HD];
__device__ __align__(16) float g_ssrc[N_NODES * 2];
__device__ __align__(16) float g_sdst[N_NODES * 2];
__device__ __align__(16) float g_rproj[NREL * HD];
__device__ __align__(16) float g_srel[NREL * 2];
__device__ __align__(16) float g_catproj[23 * HD];
__device__ __align__(16) int   g_deg[N_NODES];
__device__ __align__(16) int   g_off[N_NODES + 1];
__device__ __align__(16) int   g_cur[N_NODES];
__device__ __align__(16) int   g_esrc[N_EDGES];
__device__ __align__(16) int   g_eet[N_EDGES];
__device__ int g_bsum[128];

__device__ __forceinline__ float tanh_approx(float x) {
    float y;
    asm("tanh.approx.f32 %0, %1;" : "=f"(y) : "f"(x));
    return y;
}
__device__ __forceinline__ void fma2(unsigned long long& acc, unsigned long long x,
                                     unsigned long long w) {
    asm("fma.rn.f32x2 %0, %1, %2, %0;" : "+l"(acc) : "l"(x), "l"(w));
}
__device__ __forceinline__ unsigned long long pack2(float a, float b) {
    unsigned long long r;
    asm("mov.b64 %0, {%1, %2};" : "=l"(r) : "r"(__float_as_uint(a)), "r"(__float_as_uint(b)));
    return r;
}
__device__ __forceinline__ void unpack2(unsigned long long v, float& a, float& b) {
    unsigned lo, hi;
    asm("mov.b64 {%0, %1}, %2;" : "=r"(lo), "=r"(hi) : "l"(v));
    a = __uint_as_float(lo);
    b = __uint_as_float(hi);
}

// ---------------- prep: small GEMMs (K-split) + zero degree counters ----------------
__global__ void k_prep(const float* __restrict__ gtab, const float* __restrict__ atab,
                       const float* __restrict__ ltab, const float* __restrict__ init_rel,
                       const float* __restrict__ W,    const float* __restrict__ Wr,
                       const float* __restrict__ Wrel, const float* __restrict__ att_src,
                       float* __restrict__ rout) {
    const int b   = blockIdx.x;
    const int tid = threadIdx.x;  // 512

    if (b >= 223) {
        int i = (b - 223) * 512 + tid;
        if (i < N_NODES / 4) ((int4*)g_deg)[i] = make_int4(0, 0, 0, 0);
        return;
    }

    const int d = tid & 127;
    const int s = tid >> 7;
    const float* arow;
    const float* Bmat;
    int klen;
    if (b < 100)       { arow = init_rel + b * 400;         Bmat = Wr;   klen = 400; }
    else if (b < 200)  { arow = init_rel + (b - 100) * 400; Bmat = Wrel; klen = 400; }
    else {
        int c = b - 200;
        if (c < 3)       { arow = gtab + c * 100;        Bmat = W + 100 * HD; }
        else if (c < 12) { arow = atab + (c - 3) * 100;  Bmat = W + 200 * HD; }
        else             { arow = ltab + (c - 12) * 100; Bmat = W + 300 * HD; }
        klen = 100;
    }
    const int span = klen >> 2;
    const int k0   = s * span;
    float acc = 0.f;
#pragma unroll 5
    for (int k = k0; k < k0 + span; k++) acc += arow[k] * Bmat[k * HD + d];

    __shared__ float part[512];
    part[tid] = acc;
    __syncthreads();
    float total = 0.f;
    if (tid < 128) {
        total = part[tid] + part[tid + 128] + part[tid + 256] + part[tid + 384];
        if (b < 100)      g_rproj[b * HD + d] = total;
        else if (b < 200) rout[(b - 100) * HD + d] = total;
        else              g_catproj[(b - 200) * HD + d] = total;
    }
    if (b < 100) {
        float p = (tid < 128) ? total * att_src[d] : 0.f;
#pragma unroll
        for (int o = 16; o > 0; o >>= 1) p += __shfl_xor_sync(0xffffffffu, p, o);
        __shared__ float ws[16];
        if ((tid & 31) == 0) ws[tid >> 5] = p;
        __syncthreads();
        if (tid == 0) {
            g_srel[b * 2 + 0] = ws[0] + ws[1];
            g_srel[b * 2 + 1] = ws[2] + ws[3];
        }
    }
}

// ---------------- h projection: register-tiled SGEMM 128x128 tile ----------------
// 256 threads; thread (tn=tid&15, tm=tid>>4) computes nodes tm*8..+7 x dims tn*8..+7.
__global__ void __launch_bounds__(256) k_h(
        const float* __restrict__ id_embed, const int* __restrict__ ent_feature,
        const float* __restrict__ W, const float* __restrict__ att_src,
        const float* __restrict__ att_dst) {
    extern __shared__ float sm[];
    float* sW   = sm;             // 12800: W[100][128]
    float* sX   = sW + 12800;     // 128*52: X[node][k-chunk] padded
    float* scat = sX + 6656;      // 2944
    int*   sft  = (int*)(scat + 2944);  // 384

    const int tid = threadIdx.x;
    const int tn  = tid & 15;
    const int tm  = tid >> 4;
    const int nbase = blockIdx.x * 128;

    for (int i = tid; i < 12800; i += 256) sW[i] = W[i];
    for (int i = tid; i < 2944; i += 256) scat[i] = g_catproj[i];
    for (int i = tid; i < 384; i += 256) {
        int node = nbase + i / 3;
        if (node >= N_NODES) node = N_NODES - 1;
        sft[i] = ent_feature[node * 3 + (i % 3)];
    }
    float as_[8], ad_[8];
#pragma unroll
    for (int d = 0; d < 8; d++) {
        as_[d] = att_src[tn * 8 + d];
        ad_[d] = att_dst[tn * 8 + d];
    }

    unsigned long long acc[8][4];
#pragma unroll
    for (int n = 0; n < 8; n++)
#pragma unroll
        for (int p = 0; p < 4; p++) acc[n][p] = 0ull;

#pragma unroll 1
    for (int c = 0; c < 2; c++) {
        __syncthreads();
        for (int i = tid; i < 6400; i += 256) {
            int r = i / 50, k = i - r * 50;
            int node = nbase + r;
            if (node >= N_NODES) node = N_NODES - 1;
            sX[r * 52 + k] = id_embed[(long)node * 100 + c * 50 + k];
        }
        __syncthreads();
        const float* wb = sW + c * 50 * 128;
        const float* xb = sX + tm * 8 * 52;
#pragma unroll 5
        for (int k = 0; k < 50; k += 2) {
            ulonglong2 w0a = *(const ulonglong2*)&wb[k * 128 + tn * 8];
            ulonglong2 w0b = *(const ulonglong2*)&wb[k * 128 + tn * 8 + 4];
            ulonglong2 w1a = *(const ulonglong2*)&wb[(k + 1) * 128 + tn * 8];
            ulonglong2 w1b = *(const ulonglong2*)&wb[(k + 1) * 128 + tn * 8 + 4];
#pragma unroll
            for (int n = 0; n < 8; n++) {
                float2 xv = *(const float2*)&xb[n * 52 + k];
                unsigned long long x0 = pack2(xv.x, xv.x);
                unsigned long long x1 = pack2(xv.y, xv.y);
                fma2(acc[n][0], x0, w0a.x);
                fma2(acc[n][1], x0, w0a.y);
                fma2(acc[n][2], x0, w0b.x);
                fma2(acc[n][3], x0, w0b.y);
                fma2(acc[n][0], x1, w1a.x);
                fma2(acc[n][1], x1, w1a.y);
                fma2(acc[n][2], x1, w1b.x);
                fma2(acc[n][3], x1, w1b.y);
            }
        }
    }

    // epilogue: cat adds, store h, score dot products
#pragma unroll 1
    for (int n = 0; n < 8; n++) {
        const int nl   = tm * 8 + n;
        const int node = nbase + nl;
        const bool valid = (node < N_NODES);
        const int gf = sft[nl * 3 + 0];
        const int af = sft[nl * 3 + 1];
        const int lf = sft[nl * 3 + 2];
        float hv[8];
        unpack2(acc[n][0], hv[0], hv[1]);
        unpack2(acc[n][1], hv[2], hv[3]);
        unpack2(acc[n][2], hv[4], hv[5]);
        unpack2(acc[n][3], hv[6], hv[7]);
        const float* c0 = &scat[gf * 128 + tn * 8];
        const float* c1 = &scat[(3 + af) * 128 + tn * 8];
        const float* c2 = &scat[(12 + lf) * 128 + tn * 8];
        float4 c0a = *(const float4*)c0, c0b = *(const float4*)(c0 + 4);
        float4 c1a = *(const float4*)c1, c1b = *(const float4*)(c1 + 4);
        float4 c2a = *(const float4*)c2, c2b = *(const float4*)(c2 + 4);
        hv[0] += c0a.x + c1a.x + c2a.x;
        hv[1] += c0a.y + c1a.y + c2a.y;
        hv[2] += c0a.z + c1a.z + c2a.z;
        hv[3] += c0a.w + c1a.w + c2a.w;
        hv[4] += c0b.x + c1b.x + c2b.x;
        hv[5] += c0b.y + c1b.y + c2b.y;
        hv[6] += c0b.z + c1b.z + c2b.z;
        hv[7] += c0b.w + c1b.w + c2b.w;

        float ps = 0.f, pd = 0.f;
#pragma unroll
        for (int d = 0; d < 8; d++) {
            ps += hv[d] * as_[d];
            pd += hv[d] * ad_[d];
        }
        if (valid) {
            float* dst = &g_h[(long)node * HD + tn * 8];
            *(float4*)dst       = make_float4(hv[0], hv[1], hv[2], hv[3]);
            *(float4*)(dst + 4) = make_float4(hv[4], hv[5], hv[6], hv[7]);
        }
#pragma unroll
        for (int o = 1; o < 8; o <<= 1) {
            ps += __shfl_xor_sync(0xffffffffu, ps, o);
            pd += __shfl_xor_sync(0xffffffffu, pd, o);
        }
        if ((tn & 7) == 0 && valid) {
            const int head = tn >> 3;
            g_ssrc[node * 2 + head] = ps;
            g_sdst[node * 2 + head] = pd;
        }
    }
}

// ---------------- CSR build ----------------
__global__ void k_deg(const int* __restrict__ ei) {
    int e = blockIdx.x * 256 + threadIdx.x;
    if (e < N_EDGES) atomicAdd(&g_deg[ei[N_EDGES + e]], 1);
}

__global__ void k_scan1() {
    __shared__ int sred[256];
    const int tid = threadIdx.x;
    const int base = blockIdx.x * 1000;
    int s = 0;
    for (int i = tid; i < 1000; i += 256) s += g_deg[base + i];
    sred[tid] = s;
    __syncthreads();
    for (int o = 128; o > 0; o >>= 1) {
        if (tid < o) sred[tid] += sred[tid + o];
        __syncthreads();
    }
    if (tid == 0) g_bsum[blockIdx.x] = sred[0];
}

__global__ void k_scan2() {
    __shared__ int s[128];
    const int tid = threadIdx.x;
    int v = (tid < 100) ? g_bsum[tid] : 0;
    s[tid] = v;
    __syncthreads();
    for (int o = 1; o < 128; o <<= 1) {
        int add = (tid >= o) ? s[tid - o] : 0;
        __syncthreads();
        s[tid] += add;
        __syncthreads();
    }
    if (tid < 100) g_bsum[tid] = s[tid] - v;
    if (tid == 0) g_off[N_NODES] = N_EDGES;
}

__global__ void k_scan3() {
    __shared__ int ts[256];
    __shared__ int vals[1000];
    const int tid  = threadIdx.x;
    const int base = blockIdx.x * 1000;
    int v0 = 0, v1 = 0, v2 = 0, v3 = 0, tsum = 0;
    if (tid < 250) {
        v0 = g_deg[base + tid * 4 + 0];
        v1 = g_deg[base + tid * 4 + 1];
        v2 = g_deg[base + tid * 4 + 2];
        v3 = g_deg[base + tid * 4 + 3];
        tsum = v0 + v1 + v2 + v3;
    }
    ts[tid] = tsum;
    __syncthreads();
    for (int o = 1; o < 256; o <<= 1) {
        int add = (tid >= o) ? ts[tid - o] : 0;
        __syncthreads();
        ts[tid] += add;
        __syncthreads();
    }
    if (tid < 250) {
        int excl = ts[tid] - tsum + g_bsum[blockIdx.x];
        vals[tid * 4 + 0] = excl;
        vals[tid * 4 + 1] = excl + v0;
        vals[tid * 4 + 2] = excl + v0 + v1;
        vals[tid * 4 + 3] = excl + v0 + v1 + v2;
    }
    __syncthreads();
    for (int i = tid; i < 1000; i += 256) {
        g_off[base + i] = vals[i];
        g_cur[base + i] = vals[i];
    }
}

__global__ void k_scatter(const int* __restrict__ ei, const int* __restrict__ etyp) {
    int e = blockIdx.x * 256 + threadIdx.x;
    if (e >= N_EDGES) return;
    const int dst = ei[N_EDGES + e];
    int pos = atomicAdd(&g_cur[dst], 1);
    g_esrc[pos] = ei[e];
    g_eet[pos]  = etyp[e];
}

// ---------------- fused per-dst softmax + aggregation + tanh ----------------
__global__ void __launch_bounds__(256) k_agg(float* __restrict__ xout) {
    __shared__ float rp[NREL * HD];
    __shared__ int   sm_s[8][32];
    __shared__ int   sm_t[8][32];
    __shared__ float sm_a[8][2][32];
    const int tid = threadIdx.x;
    for (int i = tid; i < NREL * HD; i += 256) rp[i] = g_rproj[i];
    __syncthreads();

    const int lane = tid & 31;
    const int wid  = tid >> 5;
    const int head = lane >> 4;
    const int nwarps = gridDim.x * 8;

    for (int dst = blockIdx.x * 8 + wid; dst < N_NODES; dst += nwarps) {
        const int start = g_off[dst];
        const int end   = g_off[dst + 1];
        const int deg   = end - start;
        const float2 sd = ((const float2*)g_sdst)[dst];
        float4 acc = make_float4(0.f, 0.f, 0.f, 0.f);

        if (deg <= 32) {
            const int i = start + lane;
            const bool v = (i < end);
            int s = 0, t = 0;
            float l0 = -1e30f, l1 = -1e30f;
            if (v) {
                s = g_esrc[i]; t = g_eet[i];
                float2 ss = ((const float2*)g_ssrc)[s];
                float2 sr = ((const float2*)g_srel)[t];
                l0 = ss.x + sr.x + sd.x; l0 = (l0 > 0.f) ? l0 : 0.2f * l0;
                l1 = ss.y + sr.y + sd.y; l1 = (l1 > 0.f) ? l1 : 0.2f * l1;
            }
            float m0 = l0, m1 = l1;
#pragma unroll
            for (int o = 16; o > 0; o >>= 1) {
                m0 = fmaxf(m0, __shfl_xor_sync(0xffffffffu, m0, o));
                m1 = fmaxf(m1, __shfl_xor_sync(0xffffffffu, m1, o));
            }
            float e0 = v ? __expf(l0 - m0) : 0.f;
            float e1 = v ? __expf(l1 - m1) : 0.f;
            float d0 = e0, d1 = e1;
#pragma unroll
            for (int o = 16; o > 0; o >>= 1) {
                d0 += __shfl_xor_sync(0xffffffffu, d0, o);
                d1 += __shfl_xor_sync(0xffffffffu, d1, o);
            }
            sm_s[wid][lane] = s;
            sm_t[wid][lane] = t;
            sm_a[wid][0][lane] = e0 / (d0 + 1e-16f);
            sm_a[wid][1][lane] = e1 / (d1 + 1e-16f);
            __syncwarp();
            for (int j = 0; j < deg; j++) {
                const int   sj = sm_s[wid][j];
                const int   tj = sm_t[wid][j];
                const float aj = sm_a[wid][head][j];
                float4 hv = *(const float4*)&g_h[(long)sj * HD + lane * 4];
                float4 rv = *(const float4*)&rp[tj * HD + lane * 4];
                acc.x += aj * (hv.x + rv.x);
                acc.y += aj * (hv.y + rv.y);
                acc.z += aj * (hv.z + rv.z);
                acc.w += aj * (hv.w + rv.w);
            }
        } else {
            float m0 = -1e30f, m1 = -1e30f;
            for (int i = start + lane; i < end; i += 32) {
                const int s = g_esrc[i], t = g_eet[i];
                float2 ss = ((const float2*)g_ssrc)[s];
                float2 sr = ((const float2*)g_srel)[t];
                float l0 = ss.x + sr.x + sd.x; l0 = (l0 > 0.f) ? l0 : 0.2f * l0;
                float l1 = ss.y + sr.y + sd.y; l1 = (l1 > 0.f) ? l1 : 0.2f * l1;
                m0 = fmaxf(m0, l0); m1 = fmaxf(m1, l1);
            }
#pragma unroll
            for (int o = 16; o > 0; o >>= 1) {
                m0 = fmaxf(m0, __shfl_xor_sync(0xffffffffu, m0, o));
                m1 = fmaxf(m1, __shfl_xor_sync(0xffffffffu, m1, o));
            }
            float d0 = 0.f, d1 = 0.f;
            for (int i = start + lane; i < end; i += 32) {
                const int s = g_esrc[i], t = g_eet[i];
                float2 ss = ((const float2*)g_ssrc)[s];
                float2 sr = ((const float2*)g_srel)[t];
                float l0 = ss.x + sr.x + sd.x; l0 = (l0 > 0.f) ? l0 : 0.2f * l0;
                float l1 = ss.y + sr.y + sd.y; l1 = (l1 > 0.f) ? l1 : 0.2f * l1;
                d0 += __expf(l0 - m0); d1 += __expf(l1 - m1);
            }
#pragma unroll
            for (int o = 16; o > 0; o >>= 1) {
                d0 += __shfl_xor_sync(0xffffffffu, d0, o);
                d1 += __shfl_xor_sync(0xffffffffu, d1, o);
            }
            const float inv0 = 1.f / (d0 + 1e-16f);
            const float inv1 = 1.f / (d1 + 1e-16f);
            for (int base = start; base < end; base += 32) {
                const int i = base + lane;
                int s = 0, t = 0;
                float a0 = 0.f, a1 = 0.f;
                if (i < end) {
                    s = g_esrc[i]; t = g_eet[i];
                    float2 ss = ((const float2*)g_ssrc)[s];
                    float2 sr = ((const float2*)g_srel)[t];
                    float l0 = ss.x + sr.x + sd.x; l0 = (l0 > 0.f) ? l0 : 0.2f * l0;
                    float l1 = ss.y + sr.y + sd.y; l1 = (l1 > 0.f) ? l1 : 0.2f * l1;
                    a0 = __expf(l0 - m0) * inv0;
                    a1 = __expf(l1 - m1) * inv1;
                }
                sm_s[wid][lane] = s;
                sm_t[wid][lane] = t;
                sm_a[wid][0][lane] = a0;
                sm_a[wid][1][lane] = a1;
                __syncwarp();
                const int cnt = min(32, end - base);
                for (int j = 0; j < cnt; j++) {
                    const int   sj = sm_s[wid][j];
                    const int   tj = sm_t[wid][j];
                    const float aj = sm_a[wid][head][j];
                    float4 hv = *(const float4*)&g_h[(long)sj * HD + lane * 4];
                    float4 rv = *(const float4*)&rp[tj * HD + lane * 4];
                    acc.x += aj * (hv.x + rv.x);
                    acc.y += aj * (hv.y + rv.y);
                    acc.z += aj * (hv.z + rv.z);
                    acc.w += aj * (hv.w + rv.w);
                }
                __syncwarp();
            }
        }
        acc.x = tanh_approx(acc.x);
        acc.y = tanh_approx(acc.y);
        acc.z = tanh_approx(acc.z);
        acc.w = tanh_approx(acc.w);
        *(float4*)&xout[(long)dst * HD + lane * 4] = acc;
    }
}

__global__ void k_gather(const int* __restrict__ sub, const float* __restrict__ xout,
                         float* __restrict__ sub_emb) {
    int b = blockIdx.x;
    int d = threadIdx.x;
    sub_emb[(long)b * HD + d] = xout[(long)sub[b] * HD + d];
}

// ---------------- launch ----------------
extern "C" void kernel_launch(void* const* d_in, const int* in_sizes, int n_in,
                              void* d_out, int out_size) {
    const int*   edge_index  = (const int*)d_in[0];
    const int*   edge_type   = (const int*)d_in[1];
    const int*   ent_feature = (const int*)d_in[3];
    const int*   sub         = (const int*)d_in[4];
    const float* id_embed    = (const float*)d_in[7];
    const float* gender_tab  = (const float*)d_in[8];
    const float* age_tab     = (const float*)d_in[9];
    const float* level_tab   = (const float*)d_in[10];
    const float* init_rel    = (const float*)d_in[11];
    const float* W           = (const float*)d_in[12];
    const float* Wr          = (const float*)d_in[13];
    const float* att_src     = (const float*)d_in[14];
    const float* att_dst     = (const float*)d_in[15];
    const float* Wrel        = (const float*)d_in[16];

    float* out     = (float*)d_out;
    float* sub_emb = out;
    float* rout    = out + (long)BATCH * HD;
    float* xout    = rout + (long)NREL * HD;

    const int smem_kh = (12800 + 6656 + 2944) * 4 + 384 * 4;
    cudaFuncSetAttribute(k_h, cudaFuncAttributeMaxDynamicSharedMemorySize, smem_kh);

    k_prep<<<223 + 49, 512>>>(gender_tab, age_tab, level_tab, init_rel, W, Wr, Wrel,
                              att_src, rout);
    k_deg<<<(N_EDGES + 255) / 256, 256>>>(edge_index);
    k_scan1<<<100, 256>>>();
    k_h<<<(N_NODES + 127) / 128, 256, smem_kh>>>(id_embed, ent_feature, W,
                                                 att_src, att_dst);  // profiled idx 3
    k_scan2<<<1, 128>>>();
    k_scan3<<<100, 256>>>();
    k_scatter<<<(N_EDGES + 255) / 256, 256>>>(edge_index, edge_type);
    k_agg<<<592, 256>>>(xout);
    k_gather<<<BATCH, 128>>>(sub, xout, sub_emb);
}

// round 7
// speedup vs baseline: 1.3918x; 1.3918x over previous
#include <cuda_runtime.h>

#define N_NODES 100000
#define N_EDGES 400000
#define BATCH   2048
#define HD      128
#define NREL    100

// ---------------- scratch ----------------
__device__ __align__(16) float g_h[(size_t)N_NODES * HD];
__device__ __align__(16) float g_ssrc[N_NODES * 2];
__device__ __align__(16) float g_sdst[N_NODES * 2];
__device__ __align__(16) float g_rproj[NREL * HD];
__device__ __align__(16) float g_srel[NREL * 2];
__device__ __align__(16) float g_catproj[23 * HD];
__device__ __align__(16) int   g_deg[N_NODES];
__device__ __align__(16) int   g_se[N_NODES * 2];   // packed (start,end) per node
__device__ __align__(16) int   g_cur[N_NODES];
__device__ __align__(16) int   g_esrc[N_EDGES];
__device__ __align__(16) int   g_eet[N_EDGES];
__device__ int g_total;

__device__ __forceinline__ float tanh_approx(float x) {
    float y;
    asm("tanh.approx.f32 %0, %1;" : "=f"(y) : "f"(x));
    return y;
}
__device__ __forceinline__ void fma2(unsigned long long& acc, unsigned long long x,
                                     unsigned long long w) {
    asm("fma.rn.f32x2 %0, %1, %2, %0;" : "+l"(acc) : "l"(x), "l"(w));
}
__device__ __forceinline__ unsigned long long pack2(float a, float b) {
    unsigned long long r;
    asm("mov.b64 %0, {%1, %2};" : "=l"(r) : "r"(__float_as_uint(a)), "r"(__float_as_uint(b)));
    return r;
}
__device__ __forceinline__ void unpack2(unsigned long long v, float& a, float& b) {
    unsigned lo, hi;
    asm("mov.b64 {%0, %1}, %2;" : "=r"(lo), "=r"(hi) : "l"(v));
    a = __uint_as_float(lo);
    b = __uint_as_float(hi);
}

// ---------------- prep: small GEMMs (K-split) + zero counters ----------------
__global__ void k_prep(const float* __restrict__ gtab, const float* __restrict__ atab,
                       const float* __restrict__ ltab, const float* __restrict__ init_rel,
                       const float* __restrict__ W,    const float* __restrict__ Wr,
                       const float* __restrict__ Wrel, const float* __restrict__ att_src,
                       float* __restrict__ rout) {
    const int b   = blockIdx.x;
    const int tid = threadIdx.x;  // 512

    if (b >= 223) {
        int i = (b - 223) * 512 + tid;
        if (i < N_NODES / 4) ((int4*)g_deg)[i] = make_int4(0, 0, 0, 0);
        if (b == 223 && tid == 0) g_total = 0;
        return;
    }

    const int d = tid & 127;
    const int s = tid >> 7;
    const float* arow;
    const float* Bmat;
    int klen;
    if (b < 100)       { arow = init_rel + b * 400;         Bmat = Wr;   klen = 400; }
    else if (b < 200)  { arow = init_rel + (b - 100) * 400; Bmat = Wrel; klen = 400; }
    else {
        int c = b - 200;
        if (c < 3)       { arow = gtab + c * 100;        Bmat = W + 100 * HD; }
        else if (c < 12) { arow = atab + (c - 3) * 100;  Bmat = W + 200 * HD; }
        else             { arow = ltab + (c - 12) * 100; Bmat = W + 300 * HD; }
        klen = 100;
    }
    const int span = klen >> 2;
    const int k0   = s * span;
    float acc = 0.f;
#pragma unroll 5
    for (int k = k0; k < k0 + span; k++) acc += arow[k] * Bmat[k * HD + d];

    __shared__ float part[512];
    part[tid] = acc;
    __syncthreads();
    float total = 0.f;
    if (tid < 128) {
        total = part[tid] + part[tid + 128] + part[tid + 256] + part[tid + 384];
        if (b < 100)      g_rproj[b * HD + d] = total;
        else if (b < 200) rout[(b - 100) * HD + d] = total;
        else              g_catproj[(b - 200) * HD + d] = total;
    }
    if (b < 100) {
        float p = (tid < 128) ? total * att_src[d] : 0.f;
#pragma unroll
        for (int o = 16; o > 0; o >>= 1) p += __shfl_xor_sync(0xffffffffu, p, o);
        __shared__ float ws[16];
        if ((tid & 31) == 0) ws[tid >> 5] = p;
        __syncthreads();
        if (tid == 0) {
            g_srel[b * 2 + 0] = ws[0] + ws[1];
            g_srel[b * 2 + 1] = ws[2] + ws[3];
        }
    }
}

// ---------------- h projection: register-tiled SGEMM, X transposed in smem ----------------
// 256 threads; thread (tn=tid&15, tm=tid>>4) computes nodes tm*8..+7 x dims tn*8..+7.
__global__ void __launch_bounds__(256) k_h(
        const float* __restrict__ id_embed, const int* __restrict__ ent_feature,
        const float* __restrict__ W, const float* __restrict__ att_src,
        const float* __restrict__ att_dst) {
    extern __shared__ float sm[];
    float* sW   = sm;              // 12800: W[100][128]
    float* sXT  = sW + 12800;      // 6608: XT[k][node], pitch 132
    float* scat = sXT + 6608;      // 2944
    int*   sft  = (int*)(scat + 2944);  // 384

    const int tid = threadIdx.x;
    const int tn  = tid & 15;
    const int tm  = tid >> 4;
    const int nbase = blockIdx.x * 128;

    for (int i = tid; i < 12800; i += 256) sW[i] = W[i];
    for (int i = tid; i < 2944; i += 256) scat[i] = g_catproj[i];
    for (int i = tid; i < 384; i += 256) {
        int node = nbase + i / 3;
        if (node >= N_NODES) node = N_NODES - 1;
        sft[i] = ent_feature[node * 3 + (i % 3)];
    }
    float as_[8], ad_[8];
#pragma unroll
    for (int d = 0; d < 8; d++) {
        as_[d] = att_src[tn * 8 + d];
        ad_[d] = att_dst[tn * 8 + d];
    }

    unsigned long long acc[8][4];
#pragma unroll
    for (int n = 0; n < 8; n++)
#pragma unroll
        for (int p = 0; p < 4; p++) acc[n][p] = 0ull;

#pragma unroll 1
    for (int c = 0; c < 2; c++) {
        __syncthreads();
        for (int i = tid; i < 6400; i += 256) {
            int r = i / 50, k = i - r * 50;
            int node = nbase + r;
            if (node >= N_NODES) node = N_NODES - 1;
            sXT[k * 132 + r] = id_embed[(long)node * 100 + c * 50 + k];
        }
        __syncthreads();
        const float* wb = sW + c * 50 * 128;
#pragma unroll 2
        for (int k = 0; k < 50; k++) {
            ulonglong2 wpa = *(const ulonglong2*)&wb[k * 128 + tn * 8];
            ulonglong2 wpb = *(const ulonglong2*)&wb[k * 128 + tn * 8 + 4];
            float4 xa = *(const float4*)&sXT[k * 132 + tm * 8];
            float4 xb = *(const float4*)&sXT[k * 132 + tm * 8 + 4];
            float xv[8] = {xa.x, xa.y, xa.z, xa.w, xb.x, xb.y, xb.z, xb.w};
#pragma unroll
            for (int n = 0; n < 8; n++) {
                unsigned long long xx = pack2(xv[n], xv[n]);
                fma2(acc[n][0], xx, wpa.x);
                fma2(acc[n][1], xx, wpa.y);
                fma2(acc[n][2], xx, wpb.x);
                fma2(acc[n][3], xx, wpb.y);
            }
        }
    }

    // epilogue: cat adds, store h, score dot products
#pragma unroll 1
    for (int n = 0; n < 8; n++) {
        const int nl   = tm * 8 + n;
        const int node = nbase + nl;
        const bool valid = (node < N_NODES);
        const int gf = sft[nl * 3 + 0];
        const int af = sft[nl * 3 + 1];
        const int lf = sft[nl * 3 + 2];
        float hv[8];
        unpack2(acc[n][0], hv[0], hv[1]);
        unpack2(acc[n][1], hv[2], hv[3]);
        unpack2(acc[n][2], hv[4], hv[5]);
        unpack2(acc[n][3], hv[6], hv[7]);
        const float* c0 = &scat[gf * 128 + tn * 8];
        const float* c1 = &scat[(3 + af) * 128 + tn * 8];
        const float* c2 = &scat[(12 + lf) * 128 + tn * 8];
        float4 c0a = *(const float4*)c0, c0b = *(const float4*)(c0 + 4);
        float4 c1a = *(const float4*)c1, c1b = *(const float4*)(c1 + 4);
        float4 c2a = *(const float4*)c2, c2b = *(const float4*)(c2 + 4);
        hv[0] += c0a.x + c1a.x + c2a.x;
        hv[1] += c0a.y + c1a.y + c2a.y;
        hv[2] += c0a.z + c1a.z + c2a.z;
        hv[3] += c0a.w + c1a.w + c2a.w;
        hv[4] += c0b.x + c1b.x + c2b.x;
        hv[5] += c0b.y + c1b.y + c2b.y;
        hv[6] += c0b.z + c1b.z + c2b.z;
        hv[7] += c0b.w + c1b.w + c2b.w;

        float ps = 0.f, pd = 0.f;
#pragma unroll
        for (int d = 0; d < 8; d++) {
            ps += hv[d] * as_[d];
            pd += hv[d] * ad_[d];
        }
        if (valid) {
            float* dst = &g_h[(long)node * HD + tn * 8];
            *(float4*)dst       = make_float4(hv[0], hv[1], hv[2], hv[3]);
            *(float4*)(dst + 4) = make_float4(hv[4], hv[5], hv[6], hv[7]);
        }
#pragma unroll
        for (int o = 1; o < 8; o <<= 1) {
            ps += __shfl_xor_sync(0xffffffffu, ps, o);
            pd += __shfl_xor_sync(0xffffffffu, pd, o);
        }
        if ((tn & 7) == 0 && valid) {
            const int head = tn >> 3;
            g_ssrc[node * 2 + head] = ps;
            g_sdst[node * 2 + head] = pd;
        }
    }
}

// ---------------- CSR build (unordered segments) ----------------
__global__ void k_deg(const int* __restrict__ ei) {
    int e = blockIdx.x * 256 + threadIdx.x;
    if (e < N_EDGES) atomicAdd(&g_deg[ei[N_EDGES + e]], 1);
}

// warp-scan degree -> contiguous range per node via 1 atomic per warp
__global__ void k_assign() {
    const int n    = blockIdx.x * 256 + threadIdx.x;
    const int lane = threadIdx.x & 31;
    int deg = (n < N_NODES) ? g_deg[n] : 0;
    int scan = deg;
#pragma unroll
    for (int o = 1; o < 32; o <<= 1) {
        int v = __shfl_up_sync(0xffffffffu, scan, o);
        if (lane >= o) scan += v;
    }
    int wtot = __shfl_sync(0xffffffffu, scan, 31);
    int base = 0;
    if (lane == 31) base = atomicAdd(&g_total, wtot);
    base = __shfl_sync(0xffffffffu, base, 31);
    int start = base + scan - deg;
    if (n < N_NODES) {
        g_se[n * 2 + 0] = start;
        g_se[n * 2 + 1] = start + deg;
        g_cur[n] = start;
    }
}

__global__ void k_scatter(const int* __restrict__ ei, const int* __restrict__ etyp) {
    int e = blockIdx.x * 256 + threadIdx.x;
    if (e >= N_EDGES) return;
    const int dst = ei[N_EDGES + e];
    int pos = atomicAdd(&g_cur[dst], 1);
    g_esrc[pos] = ei[e];
    g_eet[pos]  = etyp[e];
}

// ---------------- fused per-dst softmax + aggregation + tanh ----------------
__global__ void __launch_bounds__(256) k_agg(float* __restrict__ xout) {
    __shared__ float rp[NREL * HD];
    __shared__ int   sm_s[8][32];
    __shared__ int   sm_t[8][32];
    __shared__ float sm_a[8][2][32];
    const int tid = threadIdx.x;
    for (int i = tid; i < NREL * HD; i += 256) rp[i] = g_rproj[i];
    __syncthreads();

    const int lane = tid & 31;
    const int wid  = tid >> 5;
    const int head = lane >> 4;
    const int nwarps = gridDim.x * 8;

    for (int dst = blockIdx.x * 8 + wid; dst < N_NODES; dst += nwarps) {
        const int2 se  = ((const int2*)g_se)[dst];
        const int start = se.x, end = se.y;
        const int deg   = end - start;
        const float2 sd = ((const float2*)g_sdst)[dst];
        float4 acc = make_float4(0.f, 0.f, 0.f, 0.f);

        if (deg <= 32) {
            const int i = start + lane;
            const bool v = (i < end);
            int s = 0, t = 0;
            float l0 = -1e30f, l1 = -1e30f;
            if (v) {
                s = g_esrc[i]; t = g_eet[i];
                float2 ss = ((const float2*)g_ssrc)[s];
                float2 sr = ((const float2*)g_srel)[t];
                l0 = ss.x + sr.x + sd.x; l0 = (l0 > 0.f) ? l0 : 0.2f * l0;
                l1 = ss.y + sr.y + sd.y; l1 = (l1 > 0.f) ? l1 : 0.2f * l1;
            }
            float m0 = l0, m1 = l1;
#pragma unroll
            for (int o = 16; o > 0; o >>= 1) {
                m0 = fmaxf(m0, __shfl_xor_sync(0xffffffffu, m0, o));
                m1 = fmaxf(m1, __shfl_xor_sync(0xffffffffu, m1, o));
            }
            float e0 = v ? __expf(l0 - m0) : 0.f;
            float e1 = v ? __expf(l1 - m1) : 0.f;
            float d0 = e0, d1 = e1;
#pragma unroll
            for (int o = 16; o > 0; o >>= 1) {
                d0 += __shfl_xor_sync(0xffffffffu, d0, o);
                d1 += __shfl_xor_sync(0xffffffffu, d1, o);
            }
            sm_s[wid][lane] = s;
            sm_t[wid][lane] = t;
            sm_a[wid][0][lane] = e0 / (d0 + 1e-16f);
            sm_a[wid][1][lane] = e1 / (d1 + 1e-16f);
            __syncwarp();
            for (int j = 0; j < deg; j++) {
                const int   sj = sm_s[wid][j];
                const int   tj = sm_t[wid][j];
                const float aj = sm_a[wid][head][j];
                float4 hv = *(const float4*)&g_h[(long)sj * HD + lane * 4];
                float4 rv = *(const float4*)&rp[tj * HD + lane * 4];
                acc.x += aj * (hv.x + rv.x);
                acc.y += aj * (hv.y + rv.y);
                acc.z += aj * (hv.z + rv.z);
                acc.w += aj * (hv.w + rv.w);
            }
        } else {
            float m0 = -1e30f, m1 = -1e30f;
            for (int i = start + lane; i < end; i += 32) {
                const int s = g_esrc[i], t = g_eet[i];
                float2 ss = ((const float2*)g_ssrc)[s];
                float2 sr = ((const float2*)g_srel)[t];
                float l0 = ss.x + sr.x + sd.x; l0 = (l0 > 0.f) ? l0 : 0.2f * l0;
                float l1 = ss.y + sr.y + sd.y; l1 = (l1 > 0.f) ? l1 : 0.2f * l1;
                m0 = fmaxf(m0, l0); m1 = fmaxf(m1, l1);
            }
#pragma unroll
            for (int o = 16; o > 0; o >>= 1) {
                m0 = fmaxf(m0, __shfl_xor_sync(0xffffffffu, m0, o));
                m1 = fmaxf(m1, __shfl_xor_sync(0xffffffffu, m1, o));
            }
            float d0 = 0.f, d1 = 0.f;
            for (int i = start + lane; i < end; i += 32) {
                const int s = g_esrc[i], t = g_eet[i];
                float2 ss = ((const float2*)g_ssrc)[s];
                float2 sr = ((const float2*)g_srel)[t];
                float l0 = ss.x + sr.x + sd.x; l0 = (l0 > 0.f) ? l0 : 0.2f * l0;
                float l1 = ss.y + sr.y + sd.y; l1 = (l1 > 0.f) ? l1 : 0.2f * l1;
                d0 += __expf(l0 - m0); d1 += __expf(l1 - m1);
            }
#pragma unroll
            for (int o = 16; o > 0; o >>= 1) {
                d0 += __shfl_xor_sync(0xffffffffu, d0, o);
                d1 += __shfl_xor_sync(0xffffffffu, d1, o);
            }
            const float inv0 = 1.f / (d0 + 1e-16f);
            const float inv1 = 1.f / (d1 + 1e-16f);
            for (int base = start; base < end; base += 32) {
                const int i = base + lane;
                int s = 0, t = 0;
                float a0 = 0.f, a1 = 0.f;
                if (i < end) {
                    s = g_esrc[i]; t = g_eet[i];
                    float2 ss = ((const float2*)g_ssrc)[s];
                    float2 sr = ((const float2*)g_srel)[t];
                    float l0 = ss.x + sr.x + sd.x; l0 = (l0 > 0.f) ? l0 : 0.2f * l0;
                    float l1 = ss.y + sr.y + sd.y; l1 = (l1 > 0.f) ? l1 : 0.2f * l1;
                    a0 = __expf(l0 - m0) * inv0;
                    a1 = __expf(l1 - m1) * inv1;
                }
                sm_s[wid][lane] = s;
                sm_t[wid][lane] = t;
                sm_a[wid][0][lane] = a0;
                sm_a[wid][1][lane] = a1;
                __syncwarp();
                const int cnt = min(32, end - base);
                for (int j = 0; j < cnt; j++) {
                    const int   sj = sm_s[wid][j];
                    const int   tj = sm_t[wid][j];
                    const float aj = sm_a[wid][head][j];
                    float4 hv = *(const float4*)&g_h[(long)sj * HD + lane * 4];
                    float4 rv = *(const float4*)&rp[tj * HD + lane * 4];
                    acc.x += aj * (hv.x + rv.x);
                    acc.y += aj * (hv.y + rv.y);
                    acc.z += aj * (hv.z + rv.z);
                    acc.w += aj * (hv.w + rv.w);
                }
                __syncwarp();
            }
        }
        acc.x = tanh_approx(acc.x);
        acc.y = tanh_approx(acc.y);
        acc.z = tanh_approx(acc.z);
        acc.w = tanh_approx(acc.w);
        *(float4*)&xout[(long)dst * HD + lane * 4] = acc;
    }
}

__global__ void k_gather(const int* __restrict__ sub, const float* __restrict__ xout,
                         float* __restrict__ sub_emb) {
    int b = blockIdx.x;
    int d = threadIdx.x;
    sub_emb[(long)b * HD + d] = xout[(long)sub[b] * HD + d];
}

// ---------------- launch ----------------
extern "C" void kernel_launch(void* const* d_in, const int* in_sizes, int n_in,
                              void* d_out, int out_size) {
    const int*   edge_index  = (const int*)d_in[0];
    const int*   edge_type   = (const int*)d_in[1];
    const int*   ent_feature = (const int*)d_in[3];
    const int*   sub         = (const int*)d_in[4];
    const float* id_embed    = (const float*)d_in[7];
    const float* gender_tab  = (const float*)d_in[8];
    const float* age_tab     = (const float*)d_in[9];
    const float* level_tab   = (const float*)d_in[10];
    const float* init_rel    = (const float*)d_in[11];
    const float* W           = (const float*)d_in[12];
    const float* Wr          = (const float*)d_in[13];
    const float* att_src     = (const float*)d_in[14];
    const float* att_dst     = (const float*)d_in[15];
    const float* Wrel        = (const float*)d_in[16];

    float* out     = (float*)d_out;
    float* sub_emb = out;
    float* rout    = out + (long)BATCH * HD;
    float* xout    = rout + (long)NREL * HD;

    // smem: W 12800 + XT 6608 + cat 2944 floats + 384 ints = 90944 B
    const int smem_kh = (12800 + 6608 + 2944) * 4 + 384 * 4;
    cudaFuncSetAttribute(k_h, cudaFuncAttributeMaxDynamicSharedMemorySize, smem_kh);

    k_prep<<<223 + 49, 512>>>(gender_tab, age_tab, level_tab, init_rel, W, Wr, Wrel,
                              att_src, rout);
    k_deg<<<(N_EDGES + 255) / 256, 256>>>(edge_index);
    k_assign<<<(N_NODES + 255) / 256, 256>>>();
    k_h<<<(N_NODES + 127) / 128, 256, smem_kh>>>(id_embed, ent_feature, W,
                                                 att_src, att_dst);  // profiled idx 3
    k_scatter<<<(N_EDGES + 255) / 256, 256>>>(edge_index, edge_type);
    k_agg<<<592, 256>>>(xout);
    k_gather<<<BATCH, 128>>>(sub, xout, sub_emb);
}

// round 8
// speedup vs baseline: 1.4916x; 1.0717x over previous
#include <cuda_runtime.h>

#define N_NODES 100000
#define N_EDGES 400000
#define BATCH   2048
#define HD      128
#define NREL    100

// ---------------- scratch ----------------
__device__ __align__(16) float g_h[(size_t)N_NODES * HD];
__device__ __align__(16) float g_ssrc[N_NODES * 2];
__device__ __align__(16) float g_sdst[N_NODES * 2];
__device__ __align__(16) float g_rproj[NREL * HD];
__device__ __align__(16) float g_srel[NREL * 2];
__device__ __align__(16) float g_catproj[23 * HD];
__device__ __align__(16) int   g_deg[N_NODES];
__device__ __align__(16) int   g_se[N_NODES * 2];   // packed (start,end) per node
__device__ __align__(16) int   g_cur[N_NODES];
__device__ __align__(16) int   g_esrc[N_EDGES];
__device__ __align__(16) int   g_eet[N_EDGES];
__device__ int g_total;

__device__ __forceinline__ float tanh_approx(float x) {
    float y;
    asm("tanh.approx.f32 %0, %1;" : "=f"(y) : "f"(x));
    return y;
}
__device__ __forceinline__ void fma2(unsigned long long& acc, unsigned long long x,
                                     unsigned long long w) {
    asm("fma.rn.f32x2 %0, %1, %2, %0;" : "+l"(acc) : "l"(x), "l"(w));
}
__device__ __forceinline__ unsigned long long pack2(float a, float b) {
    unsigned long long r;
    asm("mov.b64 %0, {%1, %2};" : "=l"(r) : "r"(__float_as_uint(a)), "r"(__float_as_uint(b)));
    return r;
}
__device__ __forceinline__ void unpack2(unsigned long long v, float& a, float& b) {
    unsigned lo, hi;
    asm("mov.b64 {%0, %1}, %2;" : "=r"(lo), "=r"(hi) : "l"(v));
    a = __uint_as_float(lo);
    b = __uint_as_float(hi);
}

// ---------------- prep: small GEMMs (K-split) + zero counters ----------------
__global__ void k_prep(const float* __restrict__ gtab, const float* __restrict__ atab,
                       const float* __restrict__ ltab, const float* __restrict__ init_rel,
                       const float* __restrict__ W,    const float* __restrict__ Wr,
                       const float* __restrict__ Wrel, const float* __restrict__ att_src,
                       float* __restrict__ rout) {
    const int b   = blockIdx.x;
    const int tid = threadIdx.x;  // 512

    if (b >= 223) {
        int i = (b - 223) * 512 + tid;
        if (i < N_NODES / 4) ((int4*)g_deg)[i] = make_int4(0, 0, 0, 0);
        if (b == 223 && tid == 0) g_total = 0;
        return;
    }

    const int d = tid & 127;
    const int s = tid >> 7;
    const float* arow;
    const float* Bmat;
    int klen;
    if (b < 100)       { arow = init_rel + b * 400;         Bmat = Wr;   klen = 400; }
    else if (b < 200)  { arow = init_rel + (b - 100) * 400; Bmat = Wrel; klen = 400; }
    else {
        int c = b - 200;
        if (c < 3)       { arow = gtab + c * 100;        Bmat = W + 100 * HD; }
        else if (c < 12) { arow = atab + (c - 3) * 100;  Bmat = W + 200 * HD; }
        else             { arow = ltab + (c - 12) * 100; Bmat = W + 300 * HD; }
        klen = 100;
    }
    const int span = klen >> 2;
    const int k0   = s * span;
    float acc = 0.f;
#pragma unroll 5
    for (int k = k0; k < k0 + span; k++) acc += arow[k] * Bmat[k * HD + d];

    __shared__ float part[512];
    part[tid] = acc;
    __syncthreads();
    float total = 0.f;
    if (tid < 128) {
        total = part[tid] + part[tid + 128] + part[tid + 256] + part[tid + 384];
        if (b < 100)      g_rproj[b * HD + d] = total;
        else if (b < 200) rout[(b - 100) * HD + d] = total;
        else              g_catproj[(b - 200) * HD + d] = total;
    }
    if (b < 100) {
        float p = (tid < 128) ? total * att_src[d] : 0.f;
#pragma unroll
        for (int o = 16; o > 0; o >>= 1) p += __shfl_xor_sync(0xffffffffu, p, o);
        __shared__ float ws[16];
        if ((tid & 31) == 0) ws[tid >> 5] = p;
        __syncthreads();
        if (tid == 0) {
            g_srel[b * 2 + 0] = ws[0] + ws[1];
            g_srel[b * 2 + 1] = ws[2] + ws[3];
        }
    }
}

// ---------------- h projection: 128 nodes x 64 dims per block (one head) ----------------
// 256 threads; thread (tn=tid&15, tm=tid>>4) computes nodes tm*8..+7 x dims tn*4..+3.
// blockIdx.x = node_tile*2 + head_half.
__global__ void __launch_bounds__(256, 3) k_h(
        const float* __restrict__ id_embed, const int* __restrict__ ent_feature,
        const float* __restrict__ W, const float* __restrict__ att_src,
        const float* __restrict__ att_dst) {
    extern __shared__ float sm[];
    float* sW   = sm;              // 6400: W[100][64-slice]
    float* sXT  = sW + 6400;       // 3300: XT[25][node] pitch 132
    float* scat = sXT + 3300;      // 1472: cat slice [23][64]
    int*   sft  = (int*)(scat + 1472);  // 384

    const int tid  = threadIdx.x;
    const int tn   = tid & 15;
    const int tm   = tid >> 4;
    const int nbase   = (blockIdx.x >> 1) * 128;
    const int half    = blockIdx.x & 1;
    const int dimbase = half * 64;

    for (int i = tid; i < 6400; i += 256) {
        int k = i >> 6, j = i & 63;
        sW[i] = W[k * HD + dimbase + j];
    }
    for (int i = tid; i < 1472; i += 256) {
        int r = i >> 6, j = i & 63;
        scat[i] = g_catproj[r * HD + dimbase + j];
    }
    for (int i = tid; i < 384; i += 256) {
        int node = nbase + i / 3;
        if (node >= N_NODES) node = N_NODES - 1;
        sft[i] = ent_feature[node * 3 + (i % 3)];
    }
    float as_[4], ad_[4];
#pragma unroll
    for (int d = 0; d < 4; d++) {
        as_[d] = att_src[dimbase + tn * 4 + d];
        ad_[d] = att_dst[dimbase + tn * 4 + d];
    }

    unsigned long long acc[8][2];
#pragma unroll
    for (int n = 0; n < 8; n++) { acc[n][0] = 0ull; acc[n][1] = 0ull; }

#pragma unroll 1
    for (int c = 0; c < 4; c++) {
        __syncthreads();
        for (int i = tid; i < 3200; i += 256) {
            int r = i / 25, k = i - r * 25;
            int node = nbase + r;
            if (node >= N_NODES) node = N_NODES - 1;
            sXT[k * 132 + r] = id_embed[(long)node * 100 + c * 25 + k];
        }
        __syncthreads();
        const float* wb = sW + c * 25 * 64;
#pragma unroll 5
        for (int k = 0; k < 25; k++) {
            ulonglong2 wp = *(const ulonglong2*)&wb[k * 64 + tn * 4];
            float4 xa = *(const float4*)&sXT[k * 132 + tm * 8];
            float4 xb = *(const float4*)&sXT[k * 132 + tm * 8 + 4];
            float xv[8] = {xa.x, xa.y, xa.z, xa.w, xb.x, xb.y, xb.z, xb.w};
#pragma unroll
            for (int n = 0; n < 8; n++) {
                unsigned long long xx = pack2(xv[n], xv[n]);
                fma2(acc[n][0], xx, wp.x);
                fma2(acc[n][1], xx, wp.y);
            }
        }
    }

    // epilogue: cat adds, store h slice, score dot partial -> full head sum
#pragma unroll 1
    for (int n = 0; n < 8; n++) {
        const int nl   = tm * 8 + n;
        const int node = nbase + nl;
        const bool valid = (node < N_NODES);
        const int gf = sft[nl * 3 + 0];
        const int af = sft[nl * 3 + 1];
        const int lf = sft[nl * 3 + 2];
        float hv[4];
        unpack2(acc[n][0], hv[0], hv[1]);
        unpack2(acc[n][1], hv[2], hv[3]);
        float4 c0 = *(const float4*)&scat[gf * 64 + tn * 4];
        float4 c1 = *(const float4*)&scat[(3 + af) * 64 + tn * 4];
        float4 c2 = *(const float4*)&scat[(12 + lf) * 64 + tn * 4];
        hv[0] += c0.x + c1.x + c2.x;
        hv[1] += c0.y + c1.y + c2.y;
        hv[2] += c0.z + c1.z + c2.z;
        hv[3] += c0.w + c1.w + c2.w;

        float ps = hv[0] * as_[0] + hv[1] * as_[1] + hv[2] * as_[2] + hv[3] * as_[3];
        float pd = hv[0] * ad_[0] + hv[1] * ad_[1] + hv[2] * ad_[2] + hv[3] * ad_[3];
        if (valid)
            *(float4*)&g_h[(long)node * HD + dimbase + tn * 4] =
                make_float4(hv[0], hv[1], hv[2], hv[3]);
#pragma unroll
        for (int o = 1; o < 16; o <<= 1) {
            ps += __shfl_xor_sync(0xffffffffu, ps, o);
            pd += __shfl_xor_sync(0xffffffffu, pd, o);
        }
        if (tn == 0 && valid) {
            g_ssrc[node * 2 + half] = ps;
            g_sdst[node * 2 + half] = pd;
        }
    }
}

// ---------------- CSR build (unordered segments) ----------------
__global__ void k_deg(const int* __restrict__ ei) {
    int e = blockIdx.x * 256 + threadIdx.x;
    if (e < N_EDGES) atomicAdd(&g_deg[ei[N_EDGES + e]], 1);
}

__global__ void k_assign() {
    const int n    = blockIdx.x * 256 + threadIdx.x;
    const int lane = threadIdx.x & 31;
    int deg = (n < N_NODES) ? g_deg[n] : 0;
    int scan = deg;
#pragma unroll
    for (int o = 1; o < 32; o <<= 1) {
        int v = __shfl_up_sync(0xffffffffu, scan, o);
        if (lane >= o) scan += v;
    }
    int wtot = __shfl_sync(0xffffffffu, scan, 31);
    int base = 0;
    if (lane == 31) base = atomicAdd(&g_total, wtot);
    base = __shfl_sync(0xffffffffu, base, 31);
    int start = base + scan - deg;
    if (n < N_NODES) {
        g_se[n * 2 + 0] = start;
        g_se[n * 2 + 1] = start + deg;
        g_cur[n] = start;
    }
}

__global__ void k_scatter(const int* __restrict__ ei, const int* __restrict__ etyp) {
    int e = blockIdx.x * 256 + threadIdx.x;
    if (e >= N_EDGES) return;
    const int dst = ei[N_EDGES + e];
    int pos = atomicAdd(&g_cur[dst], 1);
    g_esrc[pos] = ei[e];
    g_eet[pos]  = etyp[e];
}

// ---------------- fused per-dst softmax + aggregation + tanh ----------------
__global__ void __launch_bounds__(256) k_agg(float* __restrict__ xout) {
    __shared__ float rp[NREL * HD];
    __shared__ int   sm_s[8][32];
    __shared__ int   sm_t[8][32];
    __shared__ float sm_a[8][2][32];
    const int tid = threadIdx.x;
    for (int i = tid; i < NREL * HD; i += 256) rp[i] = g_rproj[i];
    __syncthreads();

    const int lane = tid & 31;
    const int wid  = tid >> 5;
    const int head = lane >> 4;
    const int nwarps = gridDim.x * 8;

    for (int dst = blockIdx.x * 8 + wid; dst < N_NODES; dst += nwarps) {
        const int2 se  = ((const int2*)g_se)[dst];
        const int start = se.x, end = se.y;
        const int deg   = end - start;
        const float2 sd = ((const float2*)g_sdst)[dst];
        float4 acc = make_float4(0.f, 0.f, 0.f, 0.f);

        if (deg <= 32) {
            const int i = start + lane;
            const bool v = (i < end);
            int s = 0, t = 0;
            float l0 = -1e30f, l1 = -1e30f;
            if (v) {
                s = g_esrc[i]; t = g_eet[i];
                float2 ss = ((const float2*)g_ssrc)[s];
                float2 sr = ((const float2*)g_srel)[t];
                l0 = ss.x + sr.x + sd.x; l0 = (l0 > 0.f) ? l0 : 0.2f * l0;
                l1 = ss.y + sr.y + sd.y; l1 = (l1 > 0.f) ? l1 : 0.2f * l1;
            }
            float m0 = l0, m1 = l1;
#pragma unroll
            for (int o = 16; o > 0; o >>= 1) {
                m0 = fmaxf(m0, __shfl_xor_sync(0xffffffffu, m0, o));
                m1 = fmaxf(m1, __shfl_xor_sync(0xffffffffu, m1, o));
            }
            float e0 = v ? __expf(l0 - m0) : 0.f;
            float e1 = v ? __expf(l1 - m1) : 0.f;
            float d0 = e0, d1 = e1;
#pragma unroll
            for (int o = 16; o > 0; o >>= 1) {
                d0 += __shfl_xor_sync(0xffffffffu, d0, o);
                d1 += __shfl_xor_sync(0xffffffffu, d1, o);
            }
            sm_s[wid][lane] = s;
            sm_t[wid][lane] = t;
            sm_a[wid][0][lane] = e0 / (d0 + 1e-16f);
            sm_a[wid][1][lane] = e1 / (d1 + 1e-16f);
            __syncwarp();
            for (int j = 0; j < deg; j++) {
                const int   sj = sm_s[wid][j];
                const int   tj = sm_t[wid][j];
                const float aj = sm_a[wid][head][j];
                float4 hv = *(const float4*)&g_h[(long)sj * HD + lane * 4];
                float4 rv = *(const float4*)&rp[tj * HD + lane * 4];
                acc.x += aj * (hv.x + rv.x);
                acc.y += aj * (hv.y + rv.y);
                acc.z += aj * (hv.z + rv.z);
                acc.w += aj * (hv.w + rv.w);
            }
        } else {
            float m0 = -1e30f, m1 = -1e30f;
            for (int i = start + lane; i < end; i += 32) {
                const int s = g_esrc[i], t = g_eet[i];
                float2 ss = ((const float2*)g_ssrc)[s];
                float2 sr = ((const float2*)g_srel)[t];
                float l0 = ss.x + sr.x + sd.x; l0 = (l0 > 0.f) ? l0 : 0.2f * l0;
                float l1 = ss.y + sr.y + sd.y; l1 = (l1 > 0.f) ? l1 : 0.2f * l1;
                m0 = fmaxf(m0, l0); m1 = fmaxf(m1, l1);
            }
#pragma unroll
            for (int o = 16; o > 0; o >>= 1) {
                m0 = fmaxf(m0, __shfl_xor_sync(0xffffffffu, m0, o));
                m1 = fmaxf(m1, __shfl_xor_sync(0xffffffffu, m1, o));
            }
            float d0 = 0.f, d1 = 0.f;
            for (int i = start + lane; i < end; i += 32) {
                const int s = g_esrc[i], t = g_eet[i];
                float2 ss = ((const float2*)g_ssrc)[s];
                float2 sr = ((const float2*)g_srel)[t];
                float l0 = ss.x + sr.x + sd.x; l0 = (l0 > 0.f) ? l0 : 0.2f * l0;
                float l1 = ss.y + sr.y + sd.y; l1 = (l1 > 0.f) ? l1 : 0.2f * l1;
                d0 += __expf(l0 - m0); d1 += __expf(l1 - m1);
            }
#pragma unroll
            for (int o = 16; o > 0; o >>= 1) {
                d0 += __shfl_xor_sync(0xffffffffu, d0, o);
                d1 += __shfl_xor_sync(0xffffffffu, d1, o);
            }
            const float inv0 = 1.f / (d0 + 1e-16f);
            const float inv1 = 1.f / (d1 + 1e-16f);
            for (int base = start; base < end; base += 32) {
                const int i = base + lane;
                int s = 0, t = 0;
                float a0 = 0.f, a1 = 0.f;
                if (i < end) {
                    s = g_esrc[i]; t = g_eet[i];
                    float2 ss = ((const float2*)g_ssrc)[s];
                    float2 sr = ((const float2*)g_srel)[t];
                    float l0 = ss.x + sr.x + sd.x; l0 = (l0 > 0.f) ? l0 : 0.2f * l0;
                    float l1 = ss.y + sr.y + sd.y; l1 = (l1 > 0.f) ? l1 : 0.2f * l1;
                    a0 = __expf(l0 - m0) * inv0;
                    a1 = __expf(l1 - m1) * inv1;
                }
                sm_s[wid][lane] = s;
                sm_t[wid][lane] = t;
                sm_a[wid][0][lane] = a0;
                sm_a[wid][1][lane] = a1;
                __syncwarp();
                const int cnt = min(32, end - base);
                for (int j = 0; j < cnt; j++) {
                    const int   sj = sm_s[wid][j];
                    const int   tj = sm_t[wid][j];
                    const float aj = sm_a[wid][head][j];
                    float4 hv = *(const float4*)&g_h[(long)sj * HD + lane * 4];
                    float4 rv = *(const float4*)&rp[tj * HD + lane * 4];
                    acc.x += aj * (hv.x + rv.x);
                    acc.y += aj * (hv.y + rv.y);
                    acc.z += aj * (hv.z + rv.z);
                    acc.w += aj * (hv.w + rv.w);
                }
                __syncwarp();
            }
        }
        acc.x = tanh_approx(acc.x);
        acc.y = tanh_approx(acc.y);
        acc.z = tanh_approx(acc.z);
        acc.w = tanh_approx(acc.w);
        *(float4*)&xout[(long)dst * HD + lane * 4] = acc;
    }
}

__global__ void k_gather(const int* __restrict__ sub, const float* __restrict__ xout,
                         float* __restrict__ sub_emb) {
    int b = blockIdx.x;
    int d = threadIdx.x;
    sub_emb[(long)b * HD + d] = xout[(long)sub[b] * HD + d];
}

// ---------------- launch ----------------
extern "C" void kernel_launch(void* const* d_in, const int* in_sizes, int n_in,
                              void* d_out, int out_size) {
    const int*   edge_index  = (const int*)d_in[0];
    const int*   edge_type   = (const int*)d_in[1];
    const int*   ent_feature = (const int*)d_in[3];
    const int*   sub         = (const int*)d_in[4];
    const float* id_embed    = (const float*)d_in[7];
    const float* gender_tab  = (const float*)d_in[8];
    const float* age_tab     = (const float*)d_in[9];
    const float* level_tab   = (const float*)d_in[10];
    const float* init_rel    = (const float*)d_in[11];
    const float* W           = (const float*)d_in[12];
    const float* Wr          = (const float*)d_in[13];
    const float* att_src     = (const float*)d_in[14];
    const float* att_dst     = (const float*)d_in[15];
    const float* Wrel        = (const float*)d_in[16];

    float* out     = (float*)d_out;
    float* sub_emb = out;
    float* rout    = out + (long)BATCH * HD;
    float* xout    = rout + (long)NREL * HD;

    // smem: 6400 + 3300 + 1472 floats + 384 ints = 46224 B
    const int smem_kh = (6400 + 3300 + 1472) * 4 + 384 * 4;
    cudaFuncSetAttribute(k_h, cudaFuncAttributeMaxDynamicSharedMemorySize, smem_kh);

    k_prep<<<223 + 49, 512>>>(gender_tab, age_tab, level_tab, init_rel, W, Wr, Wrel,
                              att_src, rout);
    k_deg<<<(N_EDGES + 255) / 256, 256>>>(edge_index);
    k_assign<<<(N_NODES + 255) / 256, 256>>>();
    k_h<<<((N_NODES + 127) / 128) * 2, 256, smem_kh>>>(id_embed, ent_feature, W,
                                                       att_src, att_dst);  // idx 3
    k_scatter<<<(N_EDGES + 255) / 256, 256>>>(edge_index, edge_type);
    k_agg<<<592, 256>>>(xout);
    k_gather<<<BATCH, 128>>>(sub, xout, sub_emb);
}

// round 9
// speedup vs baseline: 1.5100x; 1.0124x over previous
#include <cuda_runtime.h>

#define N_NODES 100000
#define N_EDGES 400000
#define BATCH   2048
#define HD      128
#define NREL    100

// ---------------- scratch ----------------
__device__ __align__(16) float g_h[(size_t)N_NODES * HD];
__device__ __align__(16) float g_ssrc[N_NODES * 2];
__device__ __align__(16) float g_sdst[N_NODES * 2];
__device__ __align__(16) float g_rproj[NREL * HD];
__device__ __align__(16) float g_srel[NREL * 2];
__device__ __align__(16) float g_catproj[23 * HD];
__device__ __align__(16) int   g_deg[N_NODES];
__device__ __align__(16) int   g_se[N_NODES * 2];   // packed (start,end) per node
__device__ __align__(16) int   g_cur[N_NODES];
__device__ __align__(16) int   g_esrc[N_EDGES];
__device__ __align__(16) int   g_eet[N_EDGES];
__device__ int g_total;

__device__ __forceinline__ float tanh_approx(float x) {
    float y;
    asm("tanh.approx.f32 %0, %1;" : "=f"(y) : "f"(x));
    return y;
}
__device__ __forceinline__ void fma2(unsigned long long& acc, unsigned long long x,
                                     unsigned long long w) {
    asm("fma.rn.f32x2 %0, %1, %2, %0;" : "+l"(acc) : "l"(x), "l"(w));
}
__device__ __forceinline__ unsigned long long pack2(float a, float b) {
    unsigned long long r;
    asm("mov.b64 %0, {%1, %2};" : "=l"(r) : "r"(__float_as_uint(a)), "r"(__float_as_uint(b)));
    return r;
}
__device__ __forceinline__ void unpack2(unsigned long long v, float& a, float& b) {
    unsigned lo, hi;
    asm("mov.b64 {%0, %1}, %2;" : "=r"(lo), "=r"(hi) : "l"(v));
    a = __uint_as_float(lo);
    b = __uint_as_float(hi);
}

// ---------------- prep: small GEMMs (K-split) + zero counters ----------------
__global__ void k_prep(const float* __restrict__ gtab, const float* __restrict__ atab,
                       const float* __restrict__ ltab, const float* __restrict__ init_rel,
                       const float* __restrict__ W,    const float* __restrict__ Wr,
                       const float* __restrict__ Wrel, const float* __restrict__ att_src,
                       float* __restrict__ rout) {
    const int b   = blockIdx.x;
    const int tid = threadIdx.x;  // 512

    if (b >= 223) {
        int i = (b - 223) * 512 + tid;
        if (i < N_NODES / 4) ((int4*)g_deg)[i] = make_int4(0, 0, 0, 0);
        if (b == 223 && tid == 0) g_total = 0;
        return;
    }

    const int d = tid & 127;
    const int s = tid >> 7;
    const float* arow;
    const float* Bmat;
    int klen;
    if (b < 100)       { arow = init_rel + b * 400;         Bmat = Wr;   klen = 400; }
    else if (b < 200)  { arow = init_rel + (b - 100) * 400; Bmat = Wrel; klen = 400; }
    else {
        int c = b - 200;
        if (c < 3)       { arow = gtab + c * 100;        Bmat = W + 100 * HD; }
        else if (c < 12) { arow = atab + (c - 3) * 100;  Bmat = W + 200 * HD; }
        else             { arow = ltab + (c - 12) * 100; Bmat = W + 300 * HD; }
        klen = 100;
    }
    const int span = klen >> 2;
    const int k0   = s * span;
    float acc = 0.f;
#pragma unroll 5
    for (int k = k0; k < k0 + span; k++) acc += arow[k] * Bmat[k * HD + d];

    __shared__ float part[512];
    part[tid] = acc;
    __syncthreads();
    float total = 0.f;
    if (tid < 128) {
        total = part[tid] + part[tid + 128] + part[tid + 256] + part[tid + 384];
        if (b < 100)      g_rproj[b * HD + d] = total;
        else if (b < 200) rout[(b - 100) * HD + d] = total;
        else              g_catproj[(b - 200) * HD + d] = total;
    }
    if (b < 100) {
        float p = (tid < 128) ? total * att_src[d] : 0.f;
#pragma unroll
        for (int o = 16; o > 0; o >>= 1) p += __shfl_xor_sync(0xffffffffu, p, o);
        __shared__ float ws[16];
        if ((tid & 31) == 0) ws[tid >> 5] = p;
        __syncthreads();
        if (tid == 0) {
            g_srel[b * 2 + 0] = ws[0] + ws[1];
            g_srel[b * 2 + 1] = ws[2] + ws[3];
        }
    }
}

// ---------------- h projection: 128 nodes x 64 dims per block (one head) ----------------
// 256 threads; thread (tn=tid&15, tm=tid>>4): nodes tm*8..+7 x dims tn*4..+3.
// f32x2 packs NODE pairs: x loads arrive pre-packed from sXT; only w is duplicated.
__global__ void __launch_bounds__(256, 4) k_h(
        const float* __restrict__ id_embed, const int* __restrict__ ent_feature,
        const float* __restrict__ W, const float* __restrict__ att_src,
        const float* __restrict__ att_dst) {
    extern __shared__ float sm[];
    float* sW   = sm;              // 6400: W[100][64-slice]
    float* sXT  = sW + 6400;       // 3300: XT[25][node] pitch 132
    float* scat = sXT + 3300;      // 1472: cat slice [23][64]
    int*   sft  = (int*)(scat + 1472);  // 384

    const int tid  = threadIdx.x;
    const int tn   = tid & 15;
    const int tm   = tid >> 4;
    const int nbase   = (blockIdx.x >> 1) * 128;
    const int half    = blockIdx.x & 1;
    const int dimbase = half * 64;

    for (int i = tid; i < 6400; i += 256) {
        int k = i >> 6, j = i & 63;
        sW[i] = W[k * HD + dimbase + j];
    }
    for (int i = tid; i < 1472; i += 256) {
        int r = i >> 6, j = i & 63;
        scat[i] = g_catproj[r * HD + dimbase + j];
    }
    for (int i = tid; i < 384; i += 256) {
        int node = nbase + i / 3;
        if (node >= N_NODES) node = N_NODES - 1;
        sft[i] = ent_feature[node * 3 + (i % 3)];
    }
    float as_[4], ad_[4];
#pragma unroll
    for (int d = 0; d < 4; d++) {
        as_[d] = att_src[dimbase + tn * 4 + d];
        ad_[d] = att_dst[dimbase + tn * 4 + d];
    }

    // acc[d][np]: dim d (tn*4+d), node-pair np (nodes tm*8+2np, +2np+1)
    unsigned long long acc[4][4];
#pragma unroll
    for (int d = 0; d < 4; d++)
#pragma unroll
        for (int np = 0; np < 4; np++) acc[d][np] = 0ull;

#pragma unroll 1
    for (int c = 0; c < 4; c++) {
        __syncthreads();
        for (int i = tid; i < 3200; i += 256) {
            int r = i / 25, k = i - r * 25;
            int node = nbase + r;
            if (node >= N_NODES) node = N_NODES - 1;
            sXT[k * 132 + r] = id_embed[(long)node * 100 + c * 25 + k];
        }
        __syncthreads();
        const float* wb = sW + c * 25 * 64;
#pragma unroll 5
        for (int k = 0; k < 25; k++) {
            float4 w4 = *(const float4*)&wb[k * 64 + tn * 4];
            ulonglong2 xp0 = *(const ulonglong2*)&sXT[k * 132 + tm * 8];      // pairs 0,1
            ulonglong2 xp1 = *(const ulonglong2*)&sXT[k * 132 + tm * 8 + 4];  // pairs 2,3
            unsigned long long w0 = pack2(w4.x, w4.x);
            unsigned long long w1 = pack2(w4.y, w4.y);
            unsigned long long w2 = pack2(w4.z, w4.z);
            unsigned long long w3 = pack2(w4.w, w4.w);
            fma2(acc[0][0], xp0.x, w0); fma2(acc[0][1], xp0.y, w0);
            fma2(acc[0][2], xp1.x, w0); fma2(acc[0][3], xp1.y, w0);
            fma2(acc[1][0], xp0.x, w1); fma2(acc[1][1], xp0.y, w1);
            fma2(acc[1][2], xp1.x, w1); fma2(acc[1][3], xp1.y, w1);
            fma2(acc[2][0], xp0.x, w2); fma2(acc[2][1], xp0.y, w2);
            fma2(acc[2][2], xp1.x, w2); fma2(acc[2][3], xp1.y, w2);
            fma2(acc[3][0], xp0.x, w3); fma2(acc[3][1], xp0.y, w3);
            fma2(acc[3][2], xp1.x, w3); fma2(acc[3][3], xp1.y, w3);
        }
    }

    // epilogue: per node-pair unpack, cat adds, store h slice, head score dots
#pragma unroll 1
    for (int np = 0; np < 4; np++) {
        float lo[4], hi[4];
#pragma unroll
        for (int d = 0; d < 4; d++) unpack2(acc[d][np], lo[d], hi[d]);
#pragma unroll
        for (int half_n = 0; half_n < 2; half_n++) {
            const float* v = half_n ? hi : lo;
            const int nl   = tm * 8 + 2 * np + half_n;
            const int node = nbase + nl;
            const bool valid = (node < N_NODES);
            const int gf = sft[nl * 3 + 0];
            const int af = sft[nl * 3 + 1];
            const int lf = sft[nl * 3 + 2];
            float4 c0 = *(const float4*)&scat[gf * 64 + tn * 4];
            float4 c1 = *(const float4*)&scat[(3 + af) * 64 + tn * 4];
            float4 c2 = *(const float4*)&scat[(12 + lf) * 64 + tn * 4];
            float hv0 = v[0] + c0.x + c1.x + c2.x;
            float hv1 = v[1] + c0.y + c1.y + c2.y;
            float hv2 = v[2] + c0.z + c1.z + c2.z;
            float hv3 = v[3] + c0.w + c1.w + c2.w;

            float ps = hv0 * as_[0] + hv1 * as_[1] + hv2 * as_[2] + hv3 * as_[3];
            float pd = hv0 * ad_[0] + hv1 * ad_[1] + hv2 * ad_[2] + hv3 * ad_[3];
            if (valid)
                *(float4*)&g_h[(long)node * HD + dimbase + tn * 4] =
                    make_float4(hv0, hv1, hv2, hv3);
#pragma unroll
            for (int o = 1; o < 16; o <<= 1) {
                ps += __shfl_xor_sync(0xffffffffu, ps, o);
                pd += __shfl_xor_sync(0xffffffffu, pd, o);
            }
            if (tn == 0 && valid) {
                g_ssrc[node * 2 + half] = ps;
                g_sdst[node * 2 + half] = pd;
            }
        }
    }
}

// ---------------- CSR build (unordered segments) ----------------
__global__ void k_deg(const int* __restrict__ ei) {
    int e = blockIdx.x * 256 + threadIdx.x;
    if (e < N_EDGES) atomicAdd(&g_deg[ei[N_EDGES + e]], 1);
}

__global__ void k_assign() {
    const int n    = blockIdx.x * 256 + threadIdx.x;
    const int lane = threadIdx.x & 31;
    int deg = (n < N_NODES) ? g_deg[n] : 0;
    int scan = deg;
#pragma unroll
    for (int o = 1; o < 32; o <<= 1) {
        int v = __shfl_up_sync(0xffffffffu, scan, o);
        if (lane >= o) scan += v;
    }
    int wtot = __shfl_sync(0xffffffffu, scan, 31);
    int base = 0;
    if (lane == 31) base = atomicAdd(&g_total, wtot);
    base = __shfl_sync(0xffffffffu, base, 31);
    int start = base + scan - deg;
    if (n < N_NODES) {
        g_se[n * 2 + 0] = start;
        g_se[n * 2 + 1] = start + deg;
        g_cur[n] = start;
    }
}

__global__ void k_scatter(const int* __restrict__ ei, const int* __restrict__ etyp) {
    int e = blockIdx.x * 256 + threadIdx.x;
    if (e >= N_EDGES) return;
    const int dst = ei[N_EDGES + e];
    int pos = atomicAdd(&g_cur[dst], 1);
    g_esrc[pos] = ei[e];
    g_eet[pos]  = etyp[e];
}

// ---------------- fused per-dst softmax + aggregation + tanh ----------------
__global__ void __launch_bounds__(256) k_agg(float* __restrict__ xout) {
    __shared__ float rp[NREL * HD];
    __shared__ int   sm_s[8][32];
    __shared__ int   sm_t[8][32];
    __shared__ float sm_a[8][2][32];
    const int tid = threadIdx.x;
    for (int i = tid; i < NREL * HD; i += 256) rp[i] = g_rproj[i];
    __syncthreads();

    const int lane = tid & 31;
    const int wid  = tid >> 5;
    const int head = lane >> 4;
    const int nwarps = gridDim.x * 8;

    for (int dst = blockIdx.x * 8 + wid; dst < N_NODES; dst += nwarps) {
        const int2 se  = ((const int2*)g_se)[dst];
        const int start = se.x, end = se.y;
        const int deg   = end - start;
        const float2 sd = ((const float2*)g_sdst)[dst];
        float4 acc = make_float4(0.f, 0.f, 0.f, 0.f);

        if (deg <= 32) {
            const int i = start + lane;
            const bool v = (i < end);
            int s = 0, t = 0;
            float l0 = -1e30f, l1 = -1e30f;
            if (v) {
                s = g_esrc[i]; t = g_eet[i];
                float2 ss = ((const float2*)g_ssrc)[s];
                float2 sr = ((const float2*)g_srel)[t];
                l0 = ss.x + sr.x + sd.x; l0 = (l0 > 0.f) ? l0 : 0.2f * l0;
                l1 = ss.y + sr.y + sd.y; l1 = (l1 > 0.f) ? l1 : 0.2f * l1;
            }
            float m0 = l0, m1 = l1;
#pragma unroll
            for (int o = 16; o > 0; o >>= 1) {
                m0 = fmaxf(m0, __shfl_xor_sync(0xffffffffu, m0, o));
                m1 = fmaxf(m1, __shfl_xor_sync(0xffffffffu, m1, o));
            }
            float e0 = v ? __expf(l0 - m0) : 0.f;
            float e1 = v ? __expf(l1 - m1) : 0.f;
            float d0 = e0, d1 = e1;
#pragma unroll
            for (int o = 16; o > 0; o >>= 1) {
                d0 += __shfl_xor_sync(0xffffffffu, d0, o);
                d1 += __shfl_xor_sync(0xffffffffu, d1, o);
            }
            sm_s[wid][lane] = s;
            sm_t[wid][lane] = t;
            sm_a[wid][0][lane] = e0 / (d0 + 1e-16f);
            sm_a[wid][1][lane] = e1 / (d1 + 1e-16f);
            __syncwarp();
            for (int j = 0; j < deg; j++) {
                const int   sj = sm_s[wid][j];
                const int   tj = sm_t[wid][j];
                const float aj = sm_a[wid][head][j];
                float4 hv = *(const float4*)&g_h[(long)sj * HD + lane * 4];
                float4 rv = *(const float4*)&rp[tj * HD + lane * 4];
                acc.x += aj * (hv.x + rv.x);
                acc.y += aj * (hv.y + rv.y);
                acc.z += aj * (hv.z + rv.z);
                acc.w += aj * (hv.w + rv.w);
            }
        } else {
            float m0 = -1e30f, m1 = -1e30f;
            for (int i = start + lane; i < end; i += 32) {
                const int s = g_esrc[i], t = g_eet[i];
                float2 ss = ((const float2*)g_ssrc)[s];
                float2 sr = ((const float2*)g_srel)[t];
                float l0 = ss.x + sr.x + sd.x; l0 = (l0 > 0.f) ? l0 : 0.2f * l0;
                float l1 = ss.y + sr.y + sd.y; l1 = (l1 > 0.f) ? l1 : 0.2f * l1;
                m0 = fmaxf(m0, l0); m1 = fmaxf(m1, l1);
            }
#pragma unroll
            for (int o = 16; o > 0; o >>= 1) {
                m0 = fmaxf(m0, __shfl_xor_sync(0xffffffffu, m0, o));
                m1 = fmaxf(m1, __shfl_xor_sync(0xffffffffu, m1, o));
            }
            float d0 = 0.f, d1 = 0.f;
            for (int i = start + lane; i < end; i += 32) {
                const int s = g_esrc[i], t = g_eet[i];
                float2 ss = ((const float2*)g_ssrc)[s];
                float2 sr = ((const float2*)g_srel)[t];
                float l0 = ss.x + sr.x + sd.x; l0 = (l0 > 0.f) ? l0 : 0.2f * l0;
                float l1 = ss.y + sr.y + sd.y; l1 = (l1 > 0.f) ? l1 : 0.2f * l1;
                d0 += __expf(l0 - m0); d1 += __expf(l1 - m1);
            }
#pragma unroll
            for (int o = 16; o > 0; o >>= 1) {
                d0 += __shfl_xor_sync(0xffffffffu, d0, o);
                d1 += __shfl_xor_sync(0xffffffffu, d1, o);
            }
            const float inv0 = 1.f / (d0 + 1e-16f);
            const float inv1 = 1.f / (d1 + 1e-16f);
            for (int base = start; base < end; base += 32) {
                const int i = base + lane;
                int s = 0, t = 0;
                float a0 = 0.f, a1 = 0.f;
                if (i < end) {
                    s = g_esrc[i]; t = g_eet[i];
                    float2 ss = ((const float2*)g_ssrc)[s];
                    float2 sr = ((const float2*)g_srel)[t];
                    float l0 = ss.x + sr.x + sd.x; l0 = (l0 > 0.f) ? l0 : 0.2f * l0;
                    float l1 = ss.y + sr.y + sd.y; l1 = (l1 > 0.f) ? l1 : 0.2f * l1;
                    a0 = __expf(l0 - m0) * inv0;
                    a1 = __expf(l1 - m1) * inv1;
                }
                sm_s[wid][lane] = s;
                sm_t[wid][lane] = t;
                sm_a[wid][0][lane] = a0;
                sm_a[wid][1][lane] = a1;
                __syncwarp();
                const int cnt = min(32, end - base);
                for (int j = 0; j < cnt; j++) {
                    const int   sj = sm_s[wid][j];
                    const int   tj = sm_t[wid][j];
                    const float aj = sm_a[wid][head][j];
                    float4 hv = *(const float4*)&g_h[(long)sj * HD + lane * 4];
                    float4 rv = *(const float4*)&rp[tj * HD + lane * 4];
                    acc.x += aj * (hv.x + rv.x);
                    acc.y += aj * (hv.y + rv.y);
                    acc.z += aj * (hv.z + rv.z);
                    acc.w += aj * (hv.w + rv.w);
                }
                __syncwarp();
            }
        }
        acc.x = tanh_approx(acc.x);
        acc.y = tanh_approx(acc.y);
        acc.z = tanh_approx(acc.z);
        acc.w = tanh_approx(acc.w);
        *(float4*)&xout[(long)dst * HD + lane * 4] = acc;
    }
}

__global__ void k_gather(const int* __restrict__ sub, const float* __restrict__ xout,
                         float* __restrict__ sub_emb) {
    int b = blockIdx.x;
    int d = threadIdx.x;
    sub_emb[(long)b * HD + d] = xout[(long)sub[b] * HD + d];
}

// ---------------- launch ----------------
extern "C" void kernel_launch(void* const* d_in, const int* in_sizes, int n_in,
                              void* d_out, int out_size) {
    const int*   edge_index  = (const int*)d_in[0];
    const int*   edge_type   = (const int*)d_in[1];
    const int*   ent_feature = (const int*)d_in[3];
    const int*   sub         = (const int*)d_in[4];
    const float* id_embed    = (const float*)d_in[7];
    const float* gender_tab  = (const float*)d_in[8];
    const float* age_tab     = (const float*)d_in[9];
    const float* level_tab   = (const float*)d_in[10];
    const float* init_rel    = (const float*)d_in[11];
    const float* W           = (const float*)d_in[12];
    const float* Wr          = (const float*)d_in[13];
    const float* att_src     = (const float*)d_in[14];
    const float* att_dst     = (const float*)d_in[15];
    const float* Wrel        = (const float*)d_in[16];

    float* out     = (float*)d_out;
    float* sub_emb = out;
    float* rout    = out + (long)BATCH * HD;
    float* xout    = rout + (long)NREL * HD;

    // smem: 6400 + 3300 + 1472 floats + 384 ints = 46224 B
    const int smem_kh = (6400 + 3300 + 1472) * 4 + 384 * 4;
    cudaFuncSetAttribute(k_h, cudaFuncAttributeMaxDynamicSharedMemorySize, smem_kh);

    k_prep<<<223 + 49, 512>>>(gender_tab, age_tab, level_tab, init_rel, W, Wr, Wrel,
                              att_src, rout);
    k_deg<<<(N_EDGES + 255) / 256, 256>>>(edge_index);
    k_assign<<<(N_NODES + 255) / 256, 256>>>();
    k_h<<<((N_NODES + 127) / 128) * 2, 256, smem_kh>>>(id_embed, ent_feature, W,
                                                       att_src, att_dst);  // idx 3
    k_scatter<<<(N_EDGES + 255) / 256, 256>>>(edge_index, edge_type);
    k_agg<<<592, 256>>>(xout);
    k_gather<<<BATCH, 128>>>(sub, xout, sub_emb);
}

// round 10
// speedup vs baseline: 1.5390x; 1.0192x over previous
#include <cuda_runtime.h>

#define N_NODES 100000
#define N_EDGES 400000
#define BATCH   2048
#define HD      128
#define NREL    100

// ---------------- scratch ----------------
__device__ __align__(16) float g_h[(size_t)N_NODES * HD];
__device__ __align__(16) float g_ssrc[N_NODES * 2];
__device__ __align__(16) float g_sdst[N_NODES * 2];
__device__ __align__(16) float g_rproj[NREL * HD];
__device__ __align__(16) float g_srel[NREL * 2];
__device__ __align__(16) float g_catproj[23 * HD];
__device__ __align__(16) int   g_deg[N_NODES];
__device__ __align__(16) int   g_se[N_NODES * 2];   // packed (start,end) per node
__device__ __align__(16) int   g_cur[N_NODES];
__device__ __align__(16) int2  g_edge[N_EDGES];     // dst-sorted (src, edge_type)
__device__ int g_total;

__device__ __forceinline__ float tanh_approx(float x) {
    float y;
    asm("tanh.approx.f32 %0, %1;" : "=f"(y) : "f"(x));
    return y;
}
__device__ __forceinline__ void fma2(unsigned long long& acc, unsigned long long x,
                                     unsigned long long w) {
    asm("fma.rn.f32x2 %0, %1, %2, %0;" : "+l"(acc) : "l"(x), "l"(w));
}
__device__ __forceinline__ unsigned long long pack2(float a, float b) {
    unsigned long long r;
    asm("mov.b64 %0, {%1, %2};" : "=l"(r) : "r"(__float_as_uint(a)), "r"(__float_as_uint(b)));
    return r;
}
__device__ __forceinline__ void unpack2(unsigned long long v, float& a, float& b) {
    unsigned lo, hi;
    asm("mov.b64 {%0, %1}, %2;" : "=r"(lo), "=r"(hi) : "l"(v));
    a = __uint_as_float(lo);
    b = __uint_as_float(hi);
}

// ---------------- prep: small GEMMs (K-split) + zero counters ----------------
__global__ void k_prep(const float* __restrict__ gtab, const float* __restrict__ atab,
                       const float* __restrict__ ltab, const float* __restrict__ init_rel,
                       const float* __restrict__ W,    const float* __restrict__ Wr,
                       const float* __restrict__ Wrel, const float* __restrict__ att_src,
                       float* __restrict__ rout) {
    const int b   = blockIdx.x;
    const int tid = threadIdx.x;  // 512

    if (b >= 223) {
        int i = (b - 223) * 512 + tid;
        if (i < N_NODES / 4) ((int4*)g_deg)[i] = make_int4(0, 0, 0, 0);
        if (b == 223 && tid == 0) g_total = 0;
        return;
    }

    const int d = tid & 127;
    const int s = tid >> 7;
    const float* arow;
    const float* Bmat;
    int klen;
    if (b < 100)       { arow = init_rel + b * 400;         Bmat = Wr;   klen = 400; }
    else if (b < 200)  { arow = init_rel + (b - 100) * 400; Bmat = Wrel; klen = 400; }
    else {
        int c = b - 200;
        if (c < 3)       { arow = gtab + c * 100;        Bmat = W + 100 * HD; }
        else if (c < 12) { arow = atab + (c - 3) * 100;  Bmat = W + 200 * HD; }
        else             { arow = ltab + (c - 12) * 100; Bmat = W + 300 * HD; }
        klen = 100;
    }
    const int span = klen >> 2;
    const int k0   = s * span;
    float acc = 0.f;
#pragma unroll 5
    for (int k = k0; k < k0 + span; k++) acc += arow[k] * Bmat[k * HD + d];

    __shared__ float part[512];
    part[tid] = acc;
    __syncthreads();
    float total = 0.f;
    if (tid < 128) {
        total = part[tid] + part[tid + 128] + part[tid + 256] + part[tid + 384];
        if (b < 100)      g_rproj[b * HD + d] = total;
        else if (b < 200) rout[(b - 100) * HD + d] = total;
        else              g_catproj[(b - 200) * HD + d] = total;
    }
    if (b < 100) {
        float p = (tid < 128) ? total * att_src[d] : 0.f;
#pragma unroll
        for (int o = 16; o > 0; o >>= 1) p += __shfl_xor_sync(0xffffffffu, p, o);
        __shared__ float ws[16];
        if ((tid & 31) == 0) ws[tid >> 5] = p;
        __syncthreads();
        if (tid == 0) {
            g_srel[b * 2 + 0] = ws[0] + ws[1];
            g_srel[b * 2 + 1] = ws[2] + ws[3];
        }
    }
}

// ---------------- h projection: 128 nodes x 64 dims, cp.async double buffer ----------------
// 256 threads; thread (tn=tid&15, tm=tid>>4): nodes tm*8..+7 x dims tn*4..+3.
#define KCH 20   // k per chunk, 5 chunks
__global__ void __launch_bounds__(256, 4) k_h(
        const float* __restrict__ id_embed, const int* __restrict__ ent_feature,
        const float* __restrict__ W, const float* __restrict__ att_src,
        const float* __restrict__ att_dst) {
    extern __shared__ float sm[];
    float* sW   = sm;                 // 6400: W[100][64-slice]
    float* sX0  = sW + 6400;          // 2640: XT[20][node] pitch 132
    float* sX1  = sX0 + 2640;         // 2640
    float* scat = sX1 + 2640;         // 1472: cat slice [23][64]
    int*   sft  = (int*)(scat + 1472);  // 384

    const int tid  = threadIdx.x;
    const int tn   = tid & 15;
    const int tm   = tid >> 4;
    const int nbase   = (blockIdx.x >> 1) * 128;
    const int half    = blockIdx.x & 1;
    const int dimbase = half * 64;

    // fill rows/cols for this thread's 10 async copies (constant across chunks)
    const int fr = tid / 2 * 0;  // placeholder (computed per j below)

    // prefetch chunk 0
    {
        int i = tid;
#pragma unroll
        for (int j = 0; j < 10; j++, i += 256) {
            int r = i / KCH, k = i - r * KCH;
            int node = nbase + r;
            if (node >= N_NODES) node = N_NODES - 1;
            unsigned dst = (unsigned)__cvta_generic_to_shared(&sX0[k * 132 + r]);
            const float* src = &id_embed[(long)node * 100 + k];
            asm volatile("cp.async.ca.shared.global [%0], [%1], 4;" :: "r"(dst), "l"(src));
        }
        asm volatile("cp.async.commit_group;");
    }

    for (int i = tid; i < 6400; i += 256) {
        int k = i >> 6, j = i & 63;
        sW[i] = W[k * HD + dimbase + j];
    }
    for (int i = tid; i < 1472; i += 256) {
        int r = i >> 6, j = i & 63;
        scat[i] = g_catproj[r * HD + dimbase + j];
    }
    for (int i = tid; i < 384; i += 256) {
        int node = nbase + i / 3;
        if (node >= N_NODES) node = N_NODES - 1;
        sft[i] = ent_feature[node * 3 + (i % 3)];
    }
    float as_[4], ad_[4];
#pragma unroll
    for (int d = 0; d < 4; d++) {
        as_[d] = att_src[dimbase + tn * 4 + d];
        ad_[d] = att_dst[dimbase + tn * 4 + d];
    }

    // acc[d][np]: dim d (tn*4+d), node-pair np (nodes tm*8+2np, +2np+1)
    unsigned long long acc[4][4];
#pragma unroll
    for (int d = 0; d < 4; d++)
#pragma unroll
        for (int np = 0; np < 4; np++) acc[d][np] = 0ull;

#pragma unroll 1
    for (int c = 0; c < 5; c++) {
        float* cur = (c & 1) ? sX1 : sX0;
        if (c + 1 < 5) {
            // prefetch next chunk (safe: prior-iteration barrier ordered reads of this buffer)
            float* nxt = ((c + 1) & 1) ? sX1 : sX0;
            int i = tid;
#pragma unroll
            for (int j = 0; j < 10; j++, i += 256) {
                int r = i / KCH, k = i - r * KCH;
                int node = nbase + r;
                if (node >= N_NODES) node = N_NODES - 1;
                unsigned dst = (unsigned)__cvta_generic_to_shared(&nxt[k * 132 + r]);
                const float* src = &id_embed[(long)node * 100 + (c + 1) * KCH + k];
                asm volatile("cp.async.ca.shared.global [%0], [%1], 4;" :: "r"(dst), "l"(src));
            }
            asm volatile("cp.async.commit_group;");
            asm volatile("cp.async.wait_group 1;");
        } else {
            asm volatile("cp.async.wait_group 0;");
        }
        __syncthreads();

        const float* wb = sW + c * KCH * 64;
#pragma unroll 5
        for (int k = 0; k < KCH; k++) {
            float4 w4 = *(const float4*)&wb[k * 64 + tn * 4];
            ulonglong2 xp0 = *(const ulonglong2*)&cur[k * 132 + tm * 8];
            ulonglong2 xp1 = *(const ulonglong2*)&cur[k * 132 + tm * 8 + 4];
            unsigned long long w0 = pack2(w4.x, w4.x);
            unsigned long long w1 = pack2(w4.y, w4.y);
            unsigned long long w2 = pack2(w4.z, w4.z);
            unsigned long long w3 = pack2(w4.w, w4.w);
            fma2(acc[0][0], xp0.x, w0); fma2(acc[0][1], xp0.y, w0);
            fma2(acc[0][2], xp1.x, w0); fma2(acc[0][3], xp1.y, w0);
            fma2(acc[1][0], xp0.x, w1); fma2(acc[1][1], xp0.y, w1);
            fma2(acc[1][2], xp1.x, w1); fma2(acc[1][3], xp1.y, w1);
            fma2(acc[2][0], xp0.x, w2); fma2(acc[2][1], xp0.y, w2);
            fma2(acc[2][2], xp1.x, w2); fma2(acc[2][3], xp1.y, w2);
            fma2(acc[3][0], xp0.x, w3); fma2(acc[3][1], xp0.y, w3);
            fma2(acc[3][2], xp1.x, w3); fma2(acc[3][3], xp1.y, w3);
        }
        __syncthreads();
    }

    // epilogue: per node-pair unpack, cat adds, store h slice, head score dots
#pragma unroll 1
    for (int np = 0; np < 4; np++) {
        float lo[4], hi[4];
#pragma unroll
        for (int d = 0; d < 4; d++) unpack2(acc[d][np], lo[d], hi[d]);
#pragma unroll
        for (int half_n = 0; half_n < 2; half_n++) {
            const float* v = half_n ? hi : lo;
            const int nl   = tm * 8 + 2 * np + half_n;
            const int node = nbase + nl;
            const bool valid = (node < N_NODES);
            const int gf = sft[nl * 3 + 0];
            const int af = sft[nl * 3 + 1];
            const int lf = sft[nl * 3 + 2];
            float4 c0 = *(const float4*)&scat[gf * 64 + tn * 4];
            float4 c1 = *(const float4*)&scat[(3 + af) * 64 + tn * 4];
            float4 c2 = *(const float4*)&scat[(12 + lf) * 64 + tn * 4];
            float hv0 = v[0] + c0.x + c1.x + c2.x;
            float hv1 = v[1] + c0.y + c1.y + c2.y;
            float hv2 = v[2] + c0.z + c1.z + c2.z;
            float hv3 = v[3] + c0.w + c1.w + c2.w;

            float ps = hv0 * as_[0] + hv1 * as_[1] + hv2 * as_[2] + hv3 * as_[3];
            float pd = hv0 * ad_[0] + hv1 * ad_[1] + hv2 * ad_[2] + hv3 * ad_[3];
            if (valid)
                *(float4*)&g_h[(long)node * HD + dimbase + tn * 4] =
                    make_float4(hv0, hv1, hv2, hv3);
#pragma unroll
            for (int o = 1; o < 16; o <<= 1) {
                ps += __shfl_xor_sync(0xffffffffu, ps, o);
                pd += __shfl_xor_sync(0xffffffffu, pd, o);
            }
            if (tn == 0 && valid) {
                g_ssrc[node * 2 + half] = ps;
                g_sdst[node * 2 + half] = pd;
            }
        }
    }
}

// ---------------- CSR build (unordered segments) ----------------
__global__ void k_deg(const int* __restrict__ ei) {
    int e = blockIdx.x * 256 + threadIdx.x;
    if (e < N_EDGES) atomicAdd(&g_deg[ei[N_EDGES + e]], 1);
}

__global__ void k_assign() {
    const int n    = blockIdx.x * 256 + threadIdx.x;
    const int lane = threadIdx.x & 31;
    int deg = (n < N_NODES) ? g_deg[n] : 0;
    int scan = deg;
#pragma unroll
    for (int o = 1; o < 32; o <<= 1) {
        int v = __shfl_up_sync(0xffffffffu, scan, o);
        if (lane >= o) scan += v;
    }
    int wtot = __shfl_sync(0xffffffffu, scan, 31);
    int base = 0;
    if (lane == 31) base = atomicAdd(&g_total, wtot);
    base = __shfl_sync(0xffffffffu, base, 31);
    int start = base + scan - deg;
    if (n < N_NODES) {
        g_se[n * 2 + 0] = start;
        g_se[n * 2 + 1] = start + deg;
        g_cur[n] = start;
    }
}

__global__ void k_scatter(const int* __restrict__ ei, const int* __restrict__ etyp) {
    int e = blockIdx.x * 256 + threadIdx.x;
    if (e >= N_EDGES) return;
    const int dst = ei[N_EDGES + e];
    int pos = atomicAdd(&g_cur[dst], 1);
    g_edge[pos] = make_int2(ei[e], etyp[e]);
}

// ---------------- fused per-dst softmax + aggregation + tanh ----------------
__global__ void __launch_bounds__(256) k_agg(float* __restrict__ xout) {
    __shared__ float rp[NREL * HD];
    __shared__ int   sm_s[8][32];
    __shared__ int   sm_t[8][32];
    __shared__ float sm_a[8][2][32];
    const int tid = threadIdx.x;
    for (int i = tid; i < NREL * HD; i += 256) rp[i] = g_rproj[i];
    __syncthreads();

    const int lane = tid & 31;
    const int wid  = tid >> 5;
    const int head = lane >> 4;
    const int nwarps = gridDim.x * 8;

    for (int dst = blockIdx.x * 8 + wid; dst < N_NODES; dst += nwarps) {
        const int2 se  = ((const int2*)g_se)[dst];
        const int start = se.x, end = se.y;
        const int deg   = end - start;
        const float2 sd = ((const float2*)g_sdst)[dst];
        float4 acc = make_float4(0.f, 0.f, 0.f, 0.f);

        if (deg <= 32) {
            const int i = start + lane;
            const bool v = (i < end);
            int s = 0, t = 0;
            float l0 = -1e30f, l1 = -1e30f;
            if (v) {
                int2 ed = g_edge[i];
                s = ed.x; t = ed.y;
                float2 ss = ((const float2*)g_ssrc)[s];
                float2 sr = ((const float2*)g_srel)[t];
                l0 = ss.x + sr.x + sd.x; l0 = (l0 > 0.f) ? l0 : 0.2f * l0;
                l1 = ss.y + sr.y + sd.y; l1 = (l1 > 0.f) ? l1 : 0.2f * l1;
            }
            float m0 = l0, m1 = l1;
#pragma unroll
            for (int o = 16; o > 0; o >>= 1) {
                m0 = fmaxf(m0, __shfl_xor_sync(0xffffffffu, m0, o));
                m1 = fmaxf(m1, __shfl_xor_sync(0xffffffffu, m1, o));
            }
            float e0 = v ? __expf(l0 - m0) : 0.f;
            float e1 = v ? __expf(l1 - m1) : 0.f;
            float d0 = e0, d1 = e1;
#pragma unroll
            for (int o = 16; o > 0; o >>= 1) {
                d0 += __shfl_xor_sync(0xffffffffu, d0, o);
                d1 += __shfl_xor_sync(0xffffffffu, d1, o);
            }
            sm_s[wid][lane] = s;
            sm_t[wid][lane] = t;
            sm_a[wid][0][lane] = e0 / (d0 + 1e-16f);
            sm_a[wid][1][lane] = e1 / (d1 + 1e-16f);
            __syncwarp();
            for (int j = 0; j < deg; j++) {
                const int   sj = sm_s[wid][j];
                const int   tj = sm_t[wid][j];
                const float aj = sm_a[wid][head][j];
                float4 hv = *(const float4*)&g_h[(long)sj * HD + lane * 4];
                float4 rv = *(const float4*)&rp[tj * HD + lane * 4];
                acc.x += aj * (hv.x + rv.x);
                acc.y += aj * (hv.y + rv.y);
                acc.z += aj * (hv.z + rv.z);
                acc.w += aj * (hv.w + rv.w);
            }
        } else {
            float m0 = -1e30f, m1 = -1e30f;
            for (int i = start + lane; i < end; i += 32) {
                int2 ed = g_edge[i];
                float2 ss = ((const float2*)g_ssrc)[ed.x];
                float2 sr = ((const float2*)g_srel)[ed.y];
                float l0 = ss.x + sr.x + sd.x; l0 = (l0 > 0.f) ? l0 : 0.2f * l0;
                float l1 = ss.y + sr.y + sd.y; l1 = (l1 > 0.f) ? l1 : 0.2f * l1;
                m0 = fmaxf(m0, l0); m1 = fmaxf(m1, l1);
            }
#pragma unroll
            for (int o = 16; o > 0; o >>= 1) {
                m0 = fmaxf(m0, __shfl_xor_sync(0xffffffffu, m0, o));
                m1 = fmaxf(m1, __shfl_xor_sync(0xffffffffu, m1, o));
            }
            float d0 = 0.f, d1 = 0.f;
            for (int i = start + lane; i < end; i += 32) {
                int2 ed = g_edge[i];
                float2 ss = ((const float2*)g_ssrc)[ed.x];
                float2 sr = ((const float2*)g_srel)[ed.y];
                float l0 = ss.x + sr.x + sd.x; l0 = (l0 > 0.f) ? l0 : 0.2f * l0;
                float l1 = ss.y + sr.y + sd.y; l1 = (l1 > 0.f) ? l1 : 0.2f * l1;
                d0 += __expf(l0 - m0); d1 += __expf(l1 - m1);
            }
#pragma unroll
            for (int o = 16; o > 0; o >>= 1) {
                d0 += __shfl_xor_sync(0xffffffffu, d0, o);
                d1 += __shfl_xor_sync(0xffffffffu, d1, o);
            }
            const float inv0 = 1.f / (d0 + 1e-16f);
            const float inv1 = 1.f / (d1 + 1e-16f);
            for (int base = start; base < end; base += 32) {
                const int i = base + lane;
                int s = 0, t = 0;
                float a0 = 0.f, a1 = 0.f;
                if (i < end) {
                    int2 ed = g_edge[i];
                    s = ed.x; t = ed.y;
                    float2 ss = ((const float2*)g_ssrc)[s];
                    float2 sr = ((const float2*)g_srel)[t];
                    float l0 = ss.x + sr.x + sd.x; l0 = (l0 > 0.f) ? l0 : 0.2f * l0;
                    float l1 = ss.y + sr.y + sd.y; l1 = (l1 > 0.f) ? l1 : 0.2f * l1;
                    a0 = __expf(l0 - m0) * inv0;
                    a1 = __expf(l1 - m1) * inv1;
                }
                sm_s[wid][lane] = s;
                sm_t[wid][lane] = t;
                sm_a[wid][0][lane] = a0;
                sm_a[wid][1][lane] = a1;
                __syncwarp();
                const int cnt = min(32, end - base);
                for (int j = 0; j < cnt; j++) {
                    const int   sj = sm_s[wid][j];
                    const int   tj = sm_t[wid][j];
                    const float aj = sm_a[wid][head][j];
                    float4 hv = *(const float4*)&g_h[(long)sj * HD + lane * 4];
                    float4 rv = *(const float4*)&rp[tj * HD + lane * 4];
                    acc.x += aj * (hv.x + rv.x);
                    acc.y += aj * (hv.y + rv.y);
                    acc.z += aj * (hv.z + rv.z);
                    acc.w += aj * (hv.w + rv.w);
                }
                __syncwarp();
            }
        }
        acc.x = tanh_approx(acc.x);
        acc.y = tanh_approx(acc.y);
        acc.z = tanh_approx(acc.z);
        acc.w = tanh_approx(acc.w);
        *(float4*)&xout[(long)dst * HD + lane * 4] = acc;
    }
}

__global__ void k_gather(const int* __restrict__ sub, const float* __restrict__ xout,
                         float* __restrict__ sub_emb) {
    int b = blockIdx.x;
    int d = threadIdx.x;
    sub_emb[(long)b * HD + d] = xout[(long)sub[b] * HD + d];
}

// ---------------- launch ----------------
extern "C" void kernel_launch(void* const* d_in, const int* in_sizes, int n_in,
                              void* d_out, int out_size) {
    const int*   edge_index  = (const int*)d_in[0];
    const int*   edge_type   = (const int*)d_in[1];
    const int*   ent_feature = (const int*)d_in[3];
    const int*   sub         = (const int*)d_in[4];
    const float* id_embed    = (const float*)d_in[7];
    const float* gender_tab  = (const float*)d_in[8];
    const float* age_tab     = (const float*)d_in[9];
    const float* level_tab   = (const float*)d_in[10];
    const float* init_rel    = (const float*)d_in[11];
    const float* W           = (const float*)d_in[12];
    const float* Wr          = (const float*)d_in[13];
    const float* att_src     = (const float*)d_in[14];
    const float* att_dst     = (const float*)d_in[15];
    const float* Wrel        = (const float*)d_in[16];

    float* out     = (float*)d_out;
    float* sub_emb = out;
    float* rout    = out + (long)BATCH * HD;
    float* xout    = rout + (long)NREL * HD;

    // smem: 6400 + 2*2640 + 1472 floats + 384 ints = 54.2 KB
    const int smem_kh = (6400 + 2 * 2640 + 1472) * 4 + 384 * 4;
    cudaFuncSetAttribute(k_h, cudaFuncAttributeMaxDynamicSharedMemorySize, smem_kh);

    k_prep<<<223 + 49, 512>>>(gender_tab, age_tab, level_tab, init_rel, W, Wr, Wrel,
                              att_src, rout);
    k_deg<<<(N_EDGES + 255) / 256, 256>>>(edge_index);
    k_assign<<<(N_NODES + 255) / 256, 256>>>();
    k_h<<<((N_NODES + 127) / 128) * 2, 256, smem_kh>>>(id_embed, ent_feature, W,
                                                       att_src, att_dst);  // idx 3
    k_scatter<<<(N_EDGES + 255) / 256, 256>>>(edge_index, edge_type);
    k_agg<<<592, 256>>>(xout);
    k_gather<<<BATCH, 128>>>(sub, xout, sub_emb);
}